// round 4
// baseline (speedup 1.0000x reference)
#include <cuda_runtime.h>
#include <math.h>

#define NN      3072
#define TWO_N   6144
#define DIM     128
#define SEQ     16
#define EE      196608
#define CC      100
#define HH      4
#define HD      32
#define INV_SQRT_HD 0.17677669529663687f
#define DELTA_T 0.1f
#define PRESERVE 0.1f

#define OUT_CAT   0
#define OUT_SKILL (TWO_N * DIM)
#define OUT_PRED  (2 * TWO_N * DIM)
#define OUT_LOSS  (2 * TWO_N * DIM + TWO_N * TWO_N)

// ----------------------------- device scratch -----------------------------
__device__ float g_dsum[DIM];
__device__ float g_ssum[DIM];
__device__ float g_seqpart[2][24][DIM];
__device__ float g_seq_att[(size_t)TWO_N * DIM];
__device__ float g_cat2[(size_t)TWO_N * 2 * DIM];
__device__ float g_fused[(size_t)TWO_N * DIM];
__device__ float g_s1[(size_t)TWO_N * DIM];
__device__ float g_s2[(size_t)TWO_N * DIM];
__device__ float g_scores[(size_t)TWO_N * TWO_N];   // general path only
__device__ float g_Adense[(size_t)TWO_N * TWO_N];   // zero between launches (exch trick)
__device__ float g_deg[TWO_N];
__device__ float g_dinv[TWO_N];
__device__ float g_degsp[TWO_N];
__device__ float g_dinvsp[TWO_N];
__device__ float g_xw[(size_t)TWO_N * DIM];
__device__ float g_agg[(size_t)TWO_N * DIM];
__device__ float g_tmpA[(size_t)TWO_N * DIM];
__device__ float g_tmpB[(size_t)TWO_N * DIM];
__device__ float g_emb[(size_t)TWO_N * DIM];
__device__ float g_sm[(size_t)TWO_N * CC];
__device__ float g_pooled[CC * DIM];
__device__ float g_G[CC * CC];
__device__ float g_kp2[CC * DIM];
__device__ float g_vp2[CC * DIM];
__device__ float g_qp2[(size_t)TWO_N * DIM];
__device__ float g_wt[DIM * DIM];
__device__ float g_acc[8];   // [0]=||A||^2 [1]=<A,SS^T> [2]=ent_sum [3]=||S^T S||^2
__device__ int   g_flag;     // 1 if sender == receiver -> scores == 0 exactly

// ----------------------------- helpers -----------------------------
__device__ __forceinline__ float blockReduceSum(float v, float* sh) {
    int t = threadIdx.x;
    sh[t] = v; __syncthreads();
    for (int s = blockDim.x >> 1; s > 0; s >>= 1) {
        if (t < s) sh[t] += sh[t + s];
        __syncthreads();
    }
    float r = sh[0]; __syncthreads();
    return r;
}
__device__ __forceinline__ float blockReduceMax(float v, float* sh) {
    int t = threadIdx.x;
    sh[t] = v; __syncthreads();
    for (int s = blockDim.x >> 1; s > 0; s >>= 1) {
        if (t < s) sh[t] = fmaxf(sh[t], sh[t + s]);
        __syncthreads();
    }
    float r = sh[0]; __syncthreads();
    return r;
}

// ----------------------------- init -----------------------------
__global__ void k_init(const float* __restrict__ sender, const float* __restrict__ receiver) {
    int i = blockIdx.x * blockDim.x + threadIdx.x;
    if (i < TWO_N) { g_deg[i] = 1.0f; g_degsp[i] = 1.0f; }
    if (i < CC * DIM) g_pooled[i] = 0.f;
    if (i < CC * CC) g_G[i] = 0.f;
    if (i < 8) g_acc[i] = 0.f;
    if (i == 0) g_flag = (sender[0] == receiver[0]) ? 1 : 0;
}

// ----------------------------- seq last-step sums -----------------------------
__global__ void k_seqsum(const float* __restrict__ demand, const float* __restrict__ supply) {
    int tensor = blockIdx.x, chunk = blockIdx.y, d = threadIdx.x;
    const float* base = tensor ? supply : demand;
    float acc = 0.f;
    int n0 = chunk * 128;
    for (int n = n0; n < n0 + 128; n++)
        acc += base[(size_t)n * SEQ * DIM + (size_t)(SEQ - 1) * DIM + d];
    g_seqpart[tensor][chunk][d] = acc;
}
__global__ void k_seqsum2() {
    int tensor = blockIdx.x, d = threadIdx.x;
    float acc = 0.f;
    for (int c = 0; c < 24; c++) acc += g_seqpart[tensor][c][d];
    (tensor ? g_ssum : g_dsum)[d] = acc;
}

// ----------------------------- MHA1 (Lq = 1, factored projections) -----------------------------
__global__ void k_mha1(const float* __restrict__ demand, const float* __restrict__ supply,
                       const float* __restrict__ skill,
                       const float* __restrict__ wi, const float* __restrict__ bi,
                       const float* __restrict__ wo, const float* __restrict__ bo) {
    int b = blockIdx.x;
    int t = threadIdx.x;  // 128
    bool dem = b < NN;
    int idx = dem ? b : b - NN;
    const float* seq = (dem ? demand : supply) + (size_t)idx * SEQ * DIM;
    const float* sum = dem ? g_dsum : g_ssum;

    __shared__ float sh_seq[SEQ][DIM];
    __shared__ float sh_qv[DIM];
    __shared__ float sh_qp[DIM];
    __shared__ float sh_u[HH][DIM + 1];
    __shared__ float sh_qb[HH];
    __shared__ float sh_l[HH][SEQ];
    __shared__ float sh_p[HH][SEQ];
    __shared__ float sh_c[HH][DIM + 1];
    __shared__ float sh_o[DIM];

    for (int i = t; i < SEQ * DIM; i += 128) sh_seq[i >> 7][i & 127] = seq[i];
    sh_qv[t] = skill[(size_t)idx * DIM + t] + sum[t];
    __syncthreads();

    {   // qp = Wq qv + bq
        const float* row = wi + (size_t)t * DIM;
        float acc = bi[t];
        #pragma unroll 8
        for (int k = 0; k < DIM; k++) acc += row[k] * sh_qv[k];
        sh_qp[t] = acc;
    }
    __syncthreads();
    {   // u[h][d] = sum_j Wk[h*32+j, d] * qp[h*32+j]
        const float* wk = wi + (size_t)DIM * DIM;
        #pragma unroll
        for (int h = 0; h < HH; h++) {
            float acc = 0.f;
            #pragma unroll 8
            for (int j = 0; j < HD; j++)
                acc += wk[(size_t)(h * HD + j) * DIM + t] * sh_qp[h * HD + j];
            sh_u[h][t] = acc;
        }
        if (t < HH) {
            const float* bk = bi + DIM;
            float acc = 0.f;
            for (int j = 0; j < HD; j++) acc += sh_qp[t * HD + j] * bk[t * HD + j];
            sh_qb[t] = acc;
        }
    }
    __syncthreads();
    if (t < HH * SEQ) {   // logits
        int h = t & 3, s = t >> 2;
        float acc = sh_qb[h];
        #pragma unroll 8
        for (int d = 0; d < DIM; d++) acc += sh_u[h][d] * sh_seq[s][d];
        sh_l[h][s] = acc * INV_SQRT_HD;
    }
    __syncthreads();
    if (t < HH) {   // softmax over SEQ
        float mx = -1e30f;
        for (int s = 0; s < SEQ; s++) mx = fmaxf(mx, sh_l[t][s]);
        float sm = 0.f;
        for (int s = 0; s < SEQ; s++) { float e = expf(sh_l[t][s] - mx); sh_p[t][s] = e; sm += e; }
        float inv = 1.f / sm;
        for (int s = 0; s < SEQ; s++) sh_p[t][s] *= inv;
    }
    __syncthreads();
    {   // c[h][t] = sum_s p[h][s] seq[s][t]
        #pragma unroll
        for (int h = 0; h < HH; h++) {
            float acc = 0.f;
            #pragma unroll
            for (int s = 0; s < SEQ; s++) acc += sh_p[h][s] * sh_seq[s][t];
            sh_c[h][t] = acc;
        }
    }
    __syncthreads();
    {   // o[t] = Wv[t,:] . c[h(t)] + bv[t]
        const float* wv = wi + (size_t)2 * DIM * DIM;
        const float* bv = bi + 2 * DIM;
        int h = t / HD;
        const float* row = wv + (size_t)t * DIM;
        float acc = bv[t];
        #pragma unroll 8
        for (int d = 0; d < DIM; d++) acc += row[d] * sh_c[h][d];
        sh_o[t] = acc;
    }
    __syncthreads();
    {   // out proj
        const float* row = wo + (size_t)t * DIM;
        float acc = bo[t];
        #pragma unroll 8
        for (int j = 0; j < DIM; j++) acc += row[j] * sh_o[j];
        g_seq_att[(size_t)b * DIM + t] = acc;
    }
}

// ----------------------------- concat builder + cat output -----------------------------
__global__ void k_cat2(const float* __restrict__ skill, float* __restrict__ out_cat) {
    int r = blockIdx.x, t = threadIdx.x;
    int idx = r < NN ? r : r - NN;
    float sv = skill[(size_t)idx * DIM + t];
    g_cat2[(size_t)r * 2 * DIM + t] = sv;
    g_cat2[(size_t)r * 2 * DIM + DIM + t] = g_seq_att[(size_t)r * DIM + t];
    out_cat[(size_t)r * DIM + t] = sv;
}

// ----------------------------- generic SGEMM: C = A[MxK] @ B[KxN] (+bias) -----------------------------
__global__ void k_sgemm(const float* __restrict__ A, const float* __restrict__ B,
                        const float* __restrict__ bias, float* __restrict__ Cmat,
                        int M, int Nn, int K, int ldc) {
    const int BM = 64, BN = 128, BK = 16;
    __shared__ float As[BK][BM];
    __shared__ float Bs[BK][BN];
    int bm = blockIdx.y * BM;
    int bn = blockIdx.x * BN;
    int tid = threadIdx.x;
    int tr = tid >> 4;
    int tc = tid & 15;
    float acc[4][8];
    #pragma unroll
    for (int r = 0; r < 4; r++)
        #pragma unroll
        for (int c = 0; c < 8; c++) acc[r][c] = 0.f;

    for (int k0 = 0; k0 < K; k0 += BK) {
        #pragma unroll
        for (int j = 0; j < 4; j++) {
            int idx = tid + 256 * j;
            int m = idx >> 4, kk = idx & 15;
            As[kk][m] = A[(size_t)(bm + m) * K + k0 + kk];
        }
        #pragma unroll
        for (int j = 0; j < 8; j++) {
            int idx = tid + 256 * j;
            int kk = idx >> 7, n = idx & 127;
            float v = 0.f;
            if (bn + n < Nn) v = B[(size_t)(k0 + kk) * Nn + bn + n];
            Bs[kk][n] = v;
        }
        __syncthreads();
        #pragma unroll
        for (int kk = 0; kk < BK; kk++) {
            float a[4], bb[8];
            #pragma unroll
            for (int r = 0; r < 4; r++) a[r] = As[kk][tr * 4 + r];
            #pragma unroll
            for (int c = 0; c < 8; c++) bb[c] = Bs[kk][tc * 8 + c];
            #pragma unroll
            for (int r = 0; r < 4; r++)
                #pragma unroll
                for (int c = 0; c < 8; c++) acc[r][c] += a[r] * bb[c];
        }
        __syncthreads();
    }
    #pragma unroll
    for (int r = 0; r < 4; r++) {
        int m = bm + tr * 4 + r;
        if (m >= M) continue;
        #pragma unroll
        for (int c = 0; c < 8; c++) {
            int n = bn + tc * 8 + c;
            if (n < Nn) {
                float v = acc[r][c];
                if (bias) v += bias[n];
                Cmat[(size_t)m * ldc + n] = v;
            }
        }
    }
}

// ----------------------------- tanh prep -----------------------------
__global__ void k_tanhprep(const float* __restrict__ sender, const float* __restrict__ receiver) {
    int i = blockIdx.x * 256 + threadIdx.x;
    if (i >= TWO_N * DIM) return;
    float f = g_fused[i];
    g_s1[i] = tanhf(sender[0] * f);
    g_s2[i] = tanhf(receiver[0] * f);
}

// ----------------------------- scores (general path only; skipped when flag) -----------------------------
__global__ void k_scores() {
    if (g_flag) return;
    int i0 = blockIdx.y * 16, j0 = blockIdx.x * 16;
    __shared__ float A1[16][DIM], A2[16][DIM], B1[16][DIM], B2[16][DIM];
    int t = threadIdx.x;  // 256
    for (int j = 0; j < 8; j++) {
        int idx = t + 256 * j;           // 0..2047
        int r = idx >> 7, c = idx & 127;
        A1[r][c] = g_s1[(size_t)(i0 + r) * DIM + c];
        A2[r][c] = g_s2[(size_t)(i0 + r) * DIM + c];
        B1[r][c] = g_s1[(size_t)(j0 + r) * DIM + c];
        B2[r][c] = g_s2[(size_t)(j0 + r) * DIM + c];
    }
    __syncthreads();
    int ti = t >> 4, tj = t & 15;
    float acc = 0.f;
    for (int k = 0; k < DIM; k++)
        acc += A1[ti][k] * B2[tj][k] - A2[ti][k] * B1[tj][k];
    g_scores[(size_t)(i0 + ti) * TWO_N + j0 + tj] = acc;
}

// ----------------------------- row softmax -> pred_g (+ col-deg), or zero-fill -----------------------------
__global__ void k_predg(float* __restrict__ out_pred) {
    int row = blockIdx.x;
    int t = threadIdx.x;  // 256
    __shared__ float sh[256];
    float4* outr = reinterpret_cast<float4*>(out_pred + (size_t)row * TWO_N);
    if (g_flag) {
        float4 z = make_float4(0.f, 0.f, 0.f, 0.f);
        for (int i = t; i < TWO_N / 4; i += 256) outr[i] = z;
        return;
    }
    float* sr = g_scores + (size_t)row * TWO_N;
    float mx = 0.f;  // relu'd values >= 0
    for (int i = t; i < TWO_N; i += 256) mx = fmaxf(mx, fmaxf(sr[i], 0.f));
    mx = blockReduceMax(mx, sh);
    float sum = 0.f;
    for (int i = t; i < TWO_N; i += 256) sum += expf(fmaxf(sr[i], 0.f) - mx);
    sum = blockReduceSum(sum, sh);
    float inv = 1.f / sum;
    for (int i = t; i < TWO_N; i += 256) {
        float p = expf(fmaxf(sr[i], 0.f) - mx) * inv;
        float pr = fmaxf(p - DELTA_T, 0.f);
        sr[i] = pr;
        out_pred[(size_t)row * TWO_N + i] = pr;
        if (pr != 0.f) atomicAdd(&g_deg[i], pr);
    }
}

__global__ void k_dinv() {
    int i = blockIdx.x * 256 + threadIdx.x;
    if (i < TWO_N) g_dinv[i] = rsqrtf(g_deg[i]);
}

// ----------------------------- dense GCN pieces -----------------------------
__global__ void k_scale_rows() {   // xw[i,:] *= dinv[i]
    int i = blockIdx.x * 256 + threadIdx.x;
    if (i >= TWO_N * DIM) return;
    g_xw[i] *= g_dinv[i >> 7];
}

__global__ void k_dense_agg() {    // general path: agg = pred^T @ xws + xws
    if (g_flag) return;
    int i0 = blockIdx.x * 32;
    int t = threadIdx.x;  // 256
    __shared__ float pcol[32];
    __shared__ float xrow[DIM];
    int dbase = t & 127, half = t >> 7;  // half in {0,1}
    float acc[16];
    #pragma unroll
    for (int r = 0; r < 16; r++) acc[r] = 0.f;
    for (int j = 0; j < TWO_N; j++) {
        if (t < 32) pcol[t] = g_scores[(size_t)j * TWO_N + i0 + t];
        else if (t >= 128 && t < 256) xrow[t - 128] = g_xw[(size_t)j * DIM + (t - 128)];
        __syncthreads();
        #pragma unroll
        for (int r = 0; r < 16; r++) acc[r] += pcol[half + 2 * r] * xrow[dbase];
        __syncthreads();
    }
    #pragma unroll
    for (int r = 0; r < 16; r++) {
        int i = i0 + half + 2 * r;
        g_agg[(size_t)i * DIM + dbase] = acc[r] + g_xw[(size_t)i * DIM + dbase];
    }
}

__global__ void k_dense_combine(const float* __restrict__ prev, float* __restrict__ dst,
                                const float* __restrict__ b0, int layer) {
    int i = blockIdx.x * 256 + threadIdx.x;
    if (i >= TWO_N * DIM) return;
    float v = g_flag ? g_xw[i] : g_agg[i];
    float out = g_dinv[i >> 7] * v + b0[layer * DIM + (i & 127)];
    dst[i] = (1.f - PRESERVE) * out + PRESERVE * prev[i];
}

// ----------------------------- sparse GCN pieces -----------------------------
__global__ void k_degsp(const int* __restrict__ dst, const float* __restrict__ w) {
    int e = blockIdx.x * 256 + threadIdx.x;
    if (e < EE) atomicAdd(&g_degsp[dst[e]], w[e]);
}
__global__ void k_dinvsp() {
    int i = blockIdx.x * 256 + threadIdx.x;
    if (i < TWO_N) {
        float d = g_degsp[i];
        g_dinvsp[i] = d > 0.f ? rsqrtf(fmaxf(d, 1e-12f)) : 0.f;
    }
}
__global__ void k_spagg_init() {   // self loop: agg[i] = dinv[i]^2 * xw[i]
    int i = blockIdx.x * 256 + threadIdx.x;
    if (i >= TWO_N * DIM) return;
    float dv = g_dinvsp[i >> 7];
    g_agg[i] = dv * dv * g_xw[i];
}
__global__ void k_scatter(const int* __restrict__ src, const int* __restrict__ dst,
                          const float* __restrict__ w) {
    long long gid = (long long)blockIdx.x * 256 + threadIdx.x;
    if (gid >= (long long)EE * DIM) return;
    int e = (int)(gid >> 7);
    int d = (int)(gid & 127);
    int s = src[e], q = dst[e];
    float coef = g_dinvsp[s] * g_dinvsp[q] * w[e];
    atomicAdd(&g_agg[(size_t)q * DIM + d], coef * g_xw[(size_t)s * DIM + d]);
}
__global__ void k_sp_combine(const float* __restrict__ prev, float* __restrict__ dstb,
                             const float* __restrict__ b1, int layer) {
    int i = blockIdx.x * 256 + threadIdx.x;
    if (i >= TWO_N * DIM) return;
    float out = g_agg[i] + b1[layer * DIM + (i & 127)];
    dstb[i] = (1.f - PRESERVE) * out + PRESERVE * prev[i];
}

__global__ void k_addemb() {
    int i = blockIdx.x * 256 + threadIdx.x;
    if (i < TWO_N * DIM) g_emb[i] = g_tmpA[i] + g_tmpB[i];
}

// ----------------------------- pooling assignment softmax + entropy -----------------------------
__global__ void k_softmax_s() {
    int r = blockIdx.x, t = threadIdx.x;  // 128 threads
    __shared__ float sh[128];
    float v = (t < CC) ? g_sm[(size_t)r * CC + t] : -1e30f;
    float mx = blockReduceMax(v, sh);
    float e = (t < CC) ? expf(v - mx) : 0.f;
    float sum = blockReduceSum(e, sh);
    float p = e / sum;
    float ent = (t < CC) ? (-p * logf(p + 1e-15f)) : 0.f;
    float es = blockReduceSum(ent, sh);
    if (t < CC) g_sm[(size_t)r * CC + t] = p;
    if (t == 0) atomicAdd(&g_acc[2], es);
}

__global__ void k_pooled() {   // pooled[c,d] = sum_i s[i,c]*emb[i,d]
    int c4 = blockIdx.x * 4;
    int i0 = blockIdx.y * 768;
    int t = threadIdx.x;  // 128
    float acc[4] = {0.f, 0.f, 0.f, 0.f};
    for (int i = i0; i < i0 + 768; i++) {
        float ev = g_emb[(size_t)i * DIM + t];
        #pragma unroll
        for (int cc = 0; cc < 4; cc++)
            acc[cc] += g_sm[(size_t)i * CC + c4 + cc] * ev;
    }
    #pragma unroll
    for (int cc = 0; cc < 4; cc++)
        atomicAdd(&g_pooled[(size_t)(c4 + cc) * DIM + t], acc[cc]);
}

// ----------------------------- link loss pieces -----------------------------
__global__ void k_scatterA(const int* __restrict__ src, const int* __restrict__ dst,
                           const float* __restrict__ w) {
    int e = blockIdx.x * 256 + threadIdx.x;
    if (e < EE) atomicAdd(&g_Adense[(size_t)src[e] * TWO_N + dst[e]], w[e]);
}
__global__ void k_normA(const int* __restrict__ src, const int* __restrict__ dst) {
    __shared__ float sh[256];
    int e = blockIdx.x * 256 + threadIdx.x;
    float v = 0.f;
    if (e < EE) {
        float old = atomicExch(&g_Adense[(size_t)src[e] * TWO_N + dst[e]], 0.f);
        v = old * old;
    }
    float s = blockReduceSum(v, sh);
    if (threadIdx.x == 0 && s != 0.f) atomicAdd(&g_acc[0], s);
}
__global__ void k_cross(const int* __restrict__ src, const int* __restrict__ dst,
                        const float* __restrict__ w) {
    __shared__ float sh[8];
    int warp = threadIdx.x >> 5, lane = threadIdx.x & 31;
    int e = blockIdx.x * 8 + warp;
    float acc = 0.f;
    if (e < EE) {
        int s = src[e], q = dst[e];
        for (int c = lane; c < CC; c += 32)
            acc += g_sm[(size_t)s * CC + c] * g_sm[(size_t)q * CC + c];
        acc *= w[e];
    }
    for (int o = 16; o > 0; o >>= 1) acc += __shfl_down_sync(0xffffffff, acc, o);
    if (lane == 0) sh[warp] = acc;
    __syncthreads();
    if (threadIdx.x == 0) {
        float s = 0.f;
        for (int i = 0; i < 8; i++) s += sh[i];
        atomicAdd(&g_acc[1], s);
    }
}
__global__ void k_gram() {   // G[c,c'] += sum_{i in chunk} s[i,c]*s[i,c']
    int c = blockIdx.x;
    int i0 = blockIdx.y * 768;
    int t = threadIdx.x;  // 128
    if (t >= CC) return;
    float acc = 0.f;
    for (int i = i0; i < i0 + 768; i++) {
        float sc = g_sm[(size_t)i * CC + c];
        acc += sc * g_sm[(size_t)i * CC + t];
    }
    atomicAdd(&g_G[c * CC + t], acc);
}
__global__ void k_gramsq() {
    __shared__ float sh[256];
    int t = threadIdx.x;
    float acc = 0.f;
    for (int i = t; i < CC * CC; i += 256) { float g = g_G[i]; acc += g * g; }
    float s = blockReduceSum(acc, sh);
    if (t == 0) g_acc[3] = s;
}
__global__ void k_finalize(float* __restrict__ out_loss) {
    float n2 = g_acc[0] - 2.f * g_acc[1] + g_acc[3];
    float link = sqrtf(fmaxf(n2, 0.f)) / ((float)TWO_N * (float)TWO_N);
    out_loss[0] = link + g_acc[2] / (float)TWO_N;
}

// ----------------------------- MHA2 -----------------------------
__global__ void k_transpose128(const float* __restrict__ wi) {  // g_wt[k,n] = wi[n,k] (first DIM rows)
    int idx = blockIdx.x * 256 + threadIdx.x;
    if (idx >= DIM * DIM) return;
    int n = idx >> 7, k = idx & 127;
    g_wt[(size_t)k * DIM + n] = wi[(size_t)n * DIM + k];
}
__global__ void k_kvproj(const float* __restrict__ wi, const float* __restrict__ bi) {
    int c = blockIdx.x;       // pooled row
    int which = blockIdx.y;   // 0=K, 1=V
    int t = threadIdx.x;      // 128
    __shared__ float prow[DIM];
    prow[t] = g_pooled[(size_t)c * DIM + t];
    __syncthreads();
    const float* row = wi + (size_t)(DIM + which * DIM + t) * DIM;
    float acc = bi[DIM + which * DIM + t];
    #pragma unroll 8
    for (int k = 0; k < DIM; k++) acc += row[k] * prow[k];
    (which ? g_vp2 : g_kp2)[(size_t)c * DIM + t] = acc;
}

#define KV_LD 129
__global__ void k_mha2(const float* __restrict__ wo, const float* __restrict__ bo,
                       float* __restrict__ out_skill) {
    extern __shared__ float smem[];
    float* kp_s = smem;                 // [CC][KV_LD]
    float* vp_s = smem + CC * KV_LD;    // [CC][KV_LD]
    __shared__ float qrow[DIM];
    __shared__ float lg[HH][CC];
    __shared__ float pp[HH][CC];
    __shared__ float o_s[DIM];
    int t = threadIdx.x;  // 128
    for (int i = t; i < CC * DIM; i += 128) {
        int j = i / DIM, d = i % DIM;
        kp_s[j * KV_LD + d] = g_kp2[i];
        vp_s[j * KV_LD + d] = g_vp2[i];
    }
    __syncthreads();
    int n0 = blockIdx.x * 16;
    for (int q = 0; q < 16; q++) {
        int n = n0 + q;
        qrow[t] = g_qp2[(size_t)n * DIM + t];
        __syncthreads();
        for (int pos = t; pos < HH * CC; pos += 128) {
            int h = pos / CC, j = pos % CC;
            float acc = 0.f;
            #pragma unroll 8
            for (int d = 0; d < HD; d++)
                acc += qrow[h * HD + d] * kp_s[j * KV_LD + h * HD + d];
            lg[h][j] = acc * INV_SQRT_HD;
        }
        __syncthreads();
        if (t < HH) {
            float mx = -1e30f;
            for (int j = 0; j < CC; j++) mx = fmaxf(mx, lg[t][j]);
            float sm = 0.f;
            for (int j = 0; j < CC; j++) { float e = expf(lg[t][j] - mx); pp[t][j] = e; sm += e; }
            float inv = 1.f / sm;
            for (int j = 0; j < CC; j++) pp[t][j] *= inv;
        }
        __syncthreads();
        {
            int h = t >> 5;
            float acc = 0.f;
            for (int j = 0; j < CC; j++) acc += pp[h][j] * vp_s[j * KV_LD + t];
            o_s[t] = acc;
        }
        __syncthreads();
        {
            const float* row = wo + (size_t)t * DIM;
            float acc = bo[t];
            #pragma unroll 8
            for (int k = 0; k < DIM; k++) acc += row[k] * o_s[k];
            out_skill[(size_t)n * DIM + t] = 2.f * g_emb[(size_t)n * DIM + t] + acc;
        }
        __syncthreads();
    }
}

// ----------------------------- host launch -----------------------------
extern "C" void kernel_launch(void* const* d_in, const int* in_sizes, int n_in,
                              void* d_out, int out_size) {
    const float* demand = (const float*)d_in[0];
    const float* supply = (const float*)d_in[1];
    const float* skill  = (const float*)d_in[2];
    const int*   eidx   = (const int*)d_in[3];
    const float* eattr  = (const float*)d_in[4];
    const float* w_fuse = (const float*)d_in[5];
    const float* b_fuse = (const float*)d_in[6];
    const float* m1wi   = (const float*)d_in[7];
    const float* m1bi   = (const float*)d_in[8];
    const float* m1wo   = (const float*)d_in[9];
    const float* m1bo   = (const float*)d_in[10];
    const float* m2wi   = (const float*)d_in[11];
    const float* m2bi   = (const float*)d_in[12];
    const float* m2wo   = (const float*)d_in[13];
    const float* m2bo   = (const float*)d_in[14];
    const float* sender = (const float*)d_in[15];
    const float* recv   = (const float*)d_in[16];
    const float* W0     = (const float*)d_in[17];
    const float* b0     = (const float*)d_in[18];
    const float* W1     = (const float*)d_in[19];
    const float* b1     = (const float*)d_in[20];
    const float* Wp     = (const float*)d_in[21];
    const float* bp     = (const float*)d_in[22];
    float* out = (float*)d_out;
    const int* src = eidx;
    const int* dst = eidx + EE;

    // no static guard: set every call (idempotent, not a stream op -> capture-safe)
    cudaFuncSetAttribute(k_mha2, cudaFuncAttributeMaxDynamicSharedMemorySize,
                         2 * CC * KV_LD * (int)sizeof(float) + 1024);

    float *p_cat2, *p_fused, *p_xw, *p_tmpA, *p_tmpB, *p_emb, *p_sm, *p_wt, *p_qp2;
    cudaGetSymbolAddress((void**)&p_cat2, g_cat2);
    cudaGetSymbolAddress((void**)&p_fused, g_fused);
    cudaGetSymbolAddress((void**)&p_xw, g_xw);
    cudaGetSymbolAddress((void**)&p_tmpA, g_tmpA);
    cudaGetSymbolAddress((void**)&p_tmpB, g_tmpB);
    cudaGetSymbolAddress((void**)&p_emb, g_emb);
    cudaGetSymbolAddress((void**)&p_sm, g_sm);
    cudaGetSymbolAddress((void**)&p_wt, g_wt);
    cudaGetSymbolAddress((void**)&p_qp2, g_qp2);

    k_init<<<64, 256>>>(sender, recv);
    k_seqsum<<<dim3(2, 24), 128>>>(demand, supply);
    k_seqsum2<<<2, 128>>>();
    k_mha1<<<TWO_N, 128>>>(demand, supply, skill, m1wi, m1bi, m1wo, m1bo);
    k_cat2<<<TWO_N, 128>>>(skill, out + OUT_CAT);
    k_sgemm<<<dim3(1, TWO_N / 64), 256>>>(p_cat2, w_fuse, b_fuse, p_fused, TWO_N, DIM, 2 * DIM, DIM);
    k_tanhprep<<<TWO_N * DIM / 256, 256>>>(sender, recv);
    k_scores<<<dim3(TWO_N / 16, TWO_N / 16), 256>>>();
    k_predg<<<TWO_N, 256>>>(out + OUT_PRED);
    k_dinv<<<24, 256>>>();

    // dense GCN (2 layers)
    for (int l = 0; l < 2; l++) {
        const float* srcbuf = (l == 0) ? p_fused : p_tmpA;
        k_sgemm<<<dim3(1, TWO_N / 64), 256>>>(srcbuf, W0 + (size_t)l * DIM * DIM, nullptr, p_xw,
                                              TWO_N, DIM, DIM, DIM);
        k_scale_rows<<<TWO_N * DIM / 256, 256>>>();
        k_dense_agg<<<TWO_N / 32, 256>>>();
        k_dense_combine<<<TWO_N * DIM / 256, 256>>>(srcbuf, p_tmpA, b0, l);
    }

    // sparse GCN (2 layers)
    k_degsp<<<EE / 256, 256>>>(dst, eattr);
    k_dinvsp<<<24, 256>>>();
    for (int l = 0; l < 2; l++) {
        const float* srcbuf = (l == 0) ? p_fused : p_tmpB;
        k_sgemm<<<dim3(1, TWO_N / 64), 256>>>(srcbuf, W1 + (size_t)l * DIM * DIM, nullptr, p_xw,
                                              TWO_N, DIM, DIM, DIM);
        k_spagg_init<<<TWO_N * DIM / 256, 256>>>();
        k_scatter<<<(unsigned)((long long)EE * DIM / 256), 256>>>(src, dst, eattr);
        k_sp_combine<<<TWO_N * DIM / 256, 256>>>(srcbuf, p_tmpB, b1, l);
    }

    k_addemb<<<TWO_N * DIM / 256, 256>>>();

    // diff-pool
    k_sgemm<<<dim3(1, TWO_N / 64), 256>>>(p_emb, Wp, bp, p_sm, TWO_N, CC, DIM, CC);
    k_softmax_s<<<TWO_N, 128>>>();
    k_pooled<<<dim3(25, 8), 128>>>();
    k_scatterA<<<EE / 256, 256>>>(src, dst, eattr);
    k_cross<<<EE / 8, 256>>>(src, dst, eattr);
    k_normA<<<EE / 256, 256>>>(src, dst);
    k_gram<<<dim3(CC, 8), 128>>>();
    k_gramsq<<<1, 256>>>();
    k_finalize<<<1, 1>>>(out + OUT_LOSS);

    // MHA2
    k_transpose128<<<DIM * DIM / 256, 256>>>(m2wi);
    k_sgemm<<<dim3(1, TWO_N / 64), 256>>>(p_emb, p_wt, m2bi, p_qp2, TWO_N, DIM, DIM, DIM);
    k_kvproj<<<dim3(CC, 2), 128>>>(m2wi, m2bi);
    k_mha2<<<TWO_N / 16, 128, 2 * CC * KV_LD * sizeof(float) + 1024>>>(m2wo, m2bo, out + OUT_SKILL);
}

// round 5
// speedup vs baseline: 2.3177x; 2.3177x over previous
#include <cuda_runtime.h>
#include <math.h>

#define NN      3072
#define TWO_N   6144
#define DIM     128
#define SEQ     16
#define EE      196608
#define CC      100
#define HH      4
#define HD      32
#define INV_SQRT_HD 0.17677669529663687f
#define DELTA_T 0.1f
#define PRESERVE 0.1f

#define OUT_CAT   0
#define OUT_SKILL (TWO_N * DIM)
#define OUT_PRED  (2 * TWO_N * DIM)
#define OUT_LOSS  (2 * TWO_N * DIM + TWO_N * TWO_N)

// ----------------------------- device scratch -----------------------------
__device__ float g_dsum[DIM];
__device__ float g_ssum[DIM];
__device__ float g_seqpart[2][24][DIM];
__device__ float g_seq_att[(size_t)TWO_N * DIM];
__device__ float g_cat2[(size_t)TWO_N * 2 * DIM];
__device__ float g_fused[(size_t)TWO_N * DIM];
__device__ float g_s1[(size_t)TWO_N * DIM];
__device__ float g_s2[(size_t)TWO_N * DIM];
__device__ float g_scores[(size_t)TWO_N * TWO_N];   // general path only
__device__ float g_Adense[(size_t)TWO_N * TWO_N];   // zero between launches (exch trick)
__device__ float g_deg[TWO_N];
__device__ float g_dinv[TWO_N];
__device__ float g_degsp[TWO_N];
__device__ float g_dinvsp[TWO_N];
__device__ float g_xw[(size_t)TWO_N * DIM];
__device__ float g_agg[(size_t)TWO_N * DIM];
__device__ float g_tmpA[(size_t)TWO_N * DIM];
__device__ float g_tmpB[(size_t)TWO_N * DIM];
__device__ float g_emb[(size_t)TWO_N * DIM];
__device__ float g_sm[(size_t)TWO_N * CC];
__device__ float g_pooled[CC * DIM];
__device__ float g_G[CC * CC];
__device__ float g_kp2[CC * DIM];
__device__ float g_vp2[CC * DIM];
__device__ float g_qp2[(size_t)TWO_N * DIM];
__device__ float g_wt[DIM * DIM];
__device__ float g_acc[8];   // [0]=||A||^2 [1]=<A,SS^T> [2]=ent_sum [3]=||S^T S||^2
__device__ int   g_flag;     // 1 if sender == receiver -> scores == 0 exactly

// CSR for sparse GCN (gather form)
__device__ int   g_csr_cnt[TWO_N];      // counts, then cursors
__device__ int   g_csr_off[TWO_N + 1];
__device__ int   g_csr_src[EE];
__device__ float g_csr_coef[EE];

// ----------------------------- helpers -----------------------------
__device__ __forceinline__ float blockReduceSum(float v, float* sh) {
    int t = threadIdx.x;
    sh[t] = v; __syncthreads();
    for (int s = blockDim.x >> 1; s > 0; s >>= 1) {
        if (t < s) sh[t] += sh[t + s];
        __syncthreads();
    }
    float r = sh[0]; __syncthreads();
    return r;
}
__device__ __forceinline__ float blockReduceMax(float v, float* sh) {
    int t = threadIdx.x;
    sh[t] = v; __syncthreads();
    for (int s = blockDim.x >> 1; s > 0; s >>= 1) {
        if (t < s) sh[t] = fmaxf(sh[t], sh[t + s]);
        __syncthreads();
    }
    float r = sh[0]; __syncthreads();
    return r;
}

// ----------------------------- init -----------------------------
__global__ void k_init(const float* __restrict__ sender, const float* __restrict__ receiver) {
    int i = blockIdx.x * blockDim.x + threadIdx.x;
    if (i < TWO_N) { g_deg[i] = 1.0f; g_degsp[i] = 1.0f; g_csr_cnt[i] = 0; }
    if (i < CC * DIM) g_pooled[i] = 0.f;
    if (i < CC * CC) g_G[i] = 0.f;
    if (i < 8) g_acc[i] = 0.f;
    if (i == 0) g_flag = (sender[0] == receiver[0]) ? 1 : 0;
}

// ----------------------------- seq last-step sums -----------------------------
__global__ void k_seqsum(const float* __restrict__ demand, const float* __restrict__ supply) {
    int tensor = blockIdx.x, chunk = blockIdx.y, d = threadIdx.x;
    const float* base = tensor ? supply : demand;
    float acc = 0.f;
    int n0 = chunk * 128;
    for (int n = n0; n < n0 + 128; n++)
        acc += base[(size_t)n * SEQ * DIM + (size_t)(SEQ - 1) * DIM + d];
    g_seqpart[tensor][chunk][d] = acc;
}
__global__ void k_seqsum2() {
    int tensor = blockIdx.x, d = threadIdx.x;
    float acc = 0.f;
    for (int c = 0; c < 24; c++) acc += g_seqpart[tensor][c][d];
    (tensor ? g_ssum : g_dsum)[d] = acc;
}

// ----------------------------- MHA1 (Lq = 1, factored projections, float4 weights) --------
__global__ void k_mha1(const float* __restrict__ demand, const float* __restrict__ supply,
                       const float* __restrict__ skill,
                       const float* __restrict__ wi, const float* __restrict__ bi,
                       const float* __restrict__ wo, const float* __restrict__ bo) {
    int b = blockIdx.x;
    int t = threadIdx.x;  // 128
    bool dem = b < NN;
    int idx = dem ? b : b - NN;
    const float* seq = (dem ? demand : supply) + (size_t)idx * SEQ * DIM;
    const float* sum = dem ? g_dsum : g_ssum;

    __shared__ float sh_seq[SEQ][DIM];
    __shared__ float sh_qv[DIM];
    __shared__ float sh_qp[DIM];
    __shared__ float sh_u[HH][DIM + 1];
    __shared__ float sh_qb[HH];
    __shared__ float sh_l[HH][SEQ];
    __shared__ float sh_p[HH][SEQ];
    __shared__ float sh_c[HH][DIM + 1];
    __shared__ float sh_o[DIM];

    for (int i = t; i < SEQ * DIM; i += 128) sh_seq[i >> 7][i & 127] = seq[i];
    sh_qv[t] = skill[(size_t)idx * DIM + t] + sum[t];
    __syncthreads();

    {   // qp = Wq qv + bq  (float4 weight row)
        const float4* row4 = reinterpret_cast<const float4*>(wi + (size_t)t * DIM);
        float acc = bi[t];
        #pragma unroll
        for (int k = 0; k < 32; k++) {
            float4 r = row4[k];
            acc += r.x * sh_qv[4 * k] + r.y * sh_qv[4 * k + 1]
                 + r.z * sh_qv[4 * k + 2] + r.w * sh_qv[4 * k + 3];
        }
        sh_qp[t] = acc;
    }
    __syncthreads();
    {   // u[h][d] = sum_j Wk[h*32+j, d] * qp[h*32+j]   (column reads, coalesced)
        const float* wk = wi + (size_t)DIM * DIM;
        #pragma unroll
        for (int h = 0; h < HH; h++) {
            float acc = 0.f;
            #pragma unroll 8
            for (int j = 0; j < HD; j++)
                acc += wk[(size_t)(h * HD + j) * DIM + t] * sh_qp[h * HD + j];
            sh_u[h][t] = acc;
        }
        if (t < HH) {
            const float* bk = bi + DIM;
            float acc = 0.f;
            for (int j = 0; j < HD; j++) acc += sh_qp[t * HD + j] * bk[t * HD + j];
            sh_qb[t] = acc;
        }
    }
    __syncthreads();
    if (t < HH * SEQ) {   // logits
        int h = t & 3, s = t >> 2;
        float acc = sh_qb[h];
        #pragma unroll 8
        for (int d = 0; d < DIM; d++) acc += sh_u[h][d] * sh_seq[s][d];
        sh_l[h][s] = acc * INV_SQRT_HD;
    }
    __syncthreads();
    if (t < HH) {   // softmax over SEQ (16 elems, cheap)
        float mx = -1e30f;
        for (int s = 0; s < SEQ; s++) mx = fmaxf(mx, sh_l[t][s]);
        float sm = 0.f;
        for (int s = 0; s < SEQ; s++) { float e = expf(sh_l[t][s] - mx); sh_p[t][s] = e; sm += e; }
        float inv = 1.f / sm;
        for (int s = 0; s < SEQ; s++) sh_p[t][s] *= inv;
    }
    __syncthreads();
    {   // c[h][t] = sum_s p[h][s] seq[s][t]
        #pragma unroll
        for (int h = 0; h < HH; h++) {
            float acc = 0.f;
            #pragma unroll
            for (int s = 0; s < SEQ; s++) acc += sh_p[h][s] * sh_seq[s][t];
            sh_c[h][t] = acc;
        }
    }
    __syncthreads();
    {   // o[t] = Wv[t,:] . c[h(t)] + bv[t]  (float4 weight row)
        const float4* row4 = reinterpret_cast<const float4*>(wi + (size_t)2 * DIM * DIM + (size_t)t * DIM);
        const float* bv = bi + 2 * DIM;
        int h = t / HD;
        float acc = bv[t];
        #pragma unroll
        for (int k = 0; k < 32; k++) {
            float4 r = row4[k];
            acc += r.x * sh_c[h][4 * k] + r.y * sh_c[h][4 * k + 1]
                 + r.z * sh_c[h][4 * k + 2] + r.w * sh_c[h][4 * k + 3];
        }
        sh_o[t] = acc;
    }
    __syncthreads();
    {   // out proj (float4 weight row)
        const float4* row4 = reinterpret_cast<const float4*>(wo + (size_t)t * DIM);
        float acc = bo[t];
        #pragma unroll
        for (int k = 0; k < 32; k++) {
            float4 r = row4[k];
            acc += r.x * sh_o[4 * k] + r.y * sh_o[4 * k + 1]
                 + r.z * sh_o[4 * k + 2] + r.w * sh_o[4 * k + 3];
        }
        g_seq_att[(size_t)b * DIM + t] = acc;
    }
}

// ----------------------------- concat builder + cat output -----------------------------
__global__ void k_cat2(const float* __restrict__ skill, float* __restrict__ out_cat) {
    int r = blockIdx.x, t = threadIdx.x;
    int idx = r < NN ? r : r - NN;
    float sv = skill[(size_t)idx * DIM + t];
    g_cat2[(size_t)r * 2 * DIM + t] = sv;
    g_cat2[(size_t)r * 2 * DIM + DIM + t] = g_seq_att[(size_t)r * DIM + t];
    out_cat[(size_t)r * DIM + t] = sv;
}

// ----------------------------- generic SGEMM: C = A[MxK] @ B[KxN] (+bias) -----------------------------
__global__ void k_sgemm(const float* __restrict__ A, const float* __restrict__ B,
                        const float* __restrict__ bias, float* __restrict__ Cmat,
                        int M, int Nn, int K, int ldc) {
    const int BM = 64, BN = 128, BK = 16;
    __shared__ float As[BK][BM];
    __shared__ float Bs[BK][BN];
    int bm = blockIdx.y * BM;
    int bn = blockIdx.x * BN;
    int tid = threadIdx.x;
    int tr = tid >> 4;
    int tc = tid & 15;
    float acc[4][8];
    #pragma unroll
    for (int r = 0; r < 4; r++)
        #pragma unroll
        for (int c = 0; c < 8; c++) acc[r][c] = 0.f;

    for (int k0 = 0; k0 < K; k0 += BK) {
        #pragma unroll
        for (int j = 0; j < 4; j++) {
            int idx = tid + 256 * j;
            int m = idx >> 4, kk = idx & 15;
            As[kk][m] = A[(size_t)(bm + m) * K + k0 + kk];
        }
        #pragma unroll
        for (int j = 0; j < 8; j++) {
            int idx = tid + 256 * j;
            int kk = idx >> 7, n = idx & 127;
            float v = 0.f;
            if (bn + n < Nn) v = B[(size_t)(k0 + kk) * Nn + bn + n];
            Bs[kk][n] = v;
        }
        __syncthreads();
        #pragma unroll
        for (int kk = 0; kk < BK; kk++) {
            float a[4], bb[8];
            #pragma unroll
            for (int r = 0; r < 4; r++) a[r] = As[kk][tr * 4 + r];
            #pragma unroll
            for (int c = 0; c < 8; c++) bb[c] = Bs[kk][tc * 8 + c];
            #pragma unroll
            for (int r = 0; r < 4; r++)
                #pragma unroll
                for (int c = 0; c < 8; c++) acc[r][c] += a[r] * bb[c];
        }
        __syncthreads();
    }
    #pragma unroll
    for (int r = 0; r < 4; r++) {
        int m = bm + tr * 4 + r;
        if (m >= M) continue;
        #pragma unroll
        for (int c = 0; c < 8; c++) {
            int n = bn + tc * 8 + c;
            if (n < Nn) {
                float v = acc[r][c];
                if (bias) v += bias[n];
                Cmat[(size_t)m * ldc + n] = v;
            }
        }
    }
}

// ----------------------------- tanh prep -----------------------------
__global__ void k_tanhprep(const float* __restrict__ sender, const float* __restrict__ receiver) {
    int i = blockIdx.x * 256 + threadIdx.x;
    if (i >= TWO_N * DIM) return;
    float f = g_fused[i];
    g_s1[i] = tanhf(sender[0] * f);
    g_s2[i] = tanhf(receiver[0] * f);
}

// ----------------------------- scores (general path only; skipped when flag) -----------------------------
__global__ void k_scores() {
    if (g_flag) return;
    int i0 = blockIdx.y * 16, j0 = blockIdx.x * 16;
    __shared__ float A1[16][DIM], A2[16][DIM], B1[16][DIM], B2[16][DIM];
    int t = threadIdx.x;  // 256
    for (int j = 0; j < 8; j++) {
        int idx = t + 256 * j;           // 0..2047
        int r = idx >> 7, c = idx & 127;
        A1[r][c] = g_s1[(size_t)(i0 + r) * DIM + c];
        A2[r][c] = g_s2[(size_t)(i0 + r) * DIM + c];
        B1[r][c] = g_s1[(size_t)(j0 + r) * DIM + c];
        B2[r][c] = g_s2[(size_t)(j0 + r) * DIM + c];
    }
    __syncthreads();
    int ti = t >> 4, tj = t & 15;
    float acc = 0.f;
    for (int k = 0; k < DIM; k++)
        acc += A1[ti][k] * B2[tj][k] - A2[ti][k] * B1[tj][k];
    g_scores[(size_t)(i0 + ti) * TWO_N + j0 + tj] = acc;
}

// ----------------------------- row softmax -> pred_g (+ col-deg), or zero-fill -----------------------------
__global__ void k_predg(float* __restrict__ out_pred) {
    int row = blockIdx.x;
    int t = threadIdx.x;  // 256
    __shared__ float sh[256];
    float4* outr = reinterpret_cast<float4*>(out_pred + (size_t)row * TWO_N);
    if (g_flag) {
        float4 z = make_float4(0.f, 0.f, 0.f, 0.f);
        for (int i = t; i < TWO_N / 4; i += 256) outr[i] = z;
        return;
    }
    float* sr = g_scores + (size_t)row * TWO_N;
    float mx = 0.f;  // relu'd values >= 0
    for (int i = t; i < TWO_N; i += 256) mx = fmaxf(mx, fmaxf(sr[i], 0.f));
    mx = blockReduceMax(mx, sh);
    float sum = 0.f;
    for (int i = t; i < TWO_N; i += 256) sum += expf(fmaxf(sr[i], 0.f) - mx);
    sum = blockReduceSum(sum, sh);
    float inv = 1.f / sum;
    for (int i = t; i < TWO_N; i += 256) {
        float p = expf(fmaxf(sr[i], 0.f) - mx) * inv;
        float pr = fmaxf(p - DELTA_T, 0.f);
        sr[i] = pr;
        out_pred[(size_t)row * TWO_N + i] = pr;
        if (pr != 0.f) atomicAdd(&g_deg[i], pr);
    }
}

__global__ void k_dinv() {
    int i = blockIdx.x * 256 + threadIdx.x;
    if (i < TWO_N) g_dinv[i] = rsqrtf(g_deg[i]);
}

// ----------------------------- dense GCN pieces -----------------------------
__global__ void k_scale_rows() {   // xw[i,:] *= dinv[i]
    int i = blockIdx.x * 256 + threadIdx.x;
    if (i >= TWO_N * DIM) return;
    g_xw[i] *= g_dinv[i >> 7];
}

__global__ void k_dense_agg() {    // general path: agg = pred^T @ xws + xws
    if (g_flag) return;
    int i0 = blockIdx.x * 32;
    int t = threadIdx.x;  // 256
    __shared__ float pcol[32];
    __shared__ float xrow[DIM];
    int dbase = t & 127, half = t >> 7;  // half in {0,1}
    float acc[16];
    #pragma unroll
    for (int r = 0; r < 16; r++) acc[r] = 0.f;
    for (int j = 0; j < TWO_N; j++) {
        if (t < 32) pcol[t] = g_scores[(size_t)j * TWO_N + i0 + t];
        else if (t >= 128 && t < 256) xrow[t - 128] = g_xw[(size_t)j * DIM + (t - 128)];
        __syncthreads();
        #pragma unroll
        for (int r = 0; r < 16; r++) acc[r] += pcol[half + 2 * r] * xrow[dbase];
        __syncthreads();
    }
    #pragma unroll
    for (int r = 0; r < 16; r++) {
        int i = i0 + half + 2 * r;
        g_agg[(size_t)i * DIM + dbase] = acc[r] + g_xw[(size_t)i * DIM + dbase];
    }
}

__global__ void k_dense_combine(const float* __restrict__ prev, float* __restrict__ dst,
                                const float* __restrict__ b0, int layer) {
    int i = blockIdx.x * 256 + threadIdx.x;
    if (i >= TWO_N * DIM) return;
    float v = g_flag ? g_xw[i] : g_agg[i];
    float out = g_dinv[i >> 7] * v + b0[layer * DIM + (i & 127)];
    dst[i] = (1.f - PRESERVE) * out + PRESERVE * prev[i];
}

// ----------------------------- sparse GCN: CSR build + gather -----------------------------
__global__ void k_degsp(const int* __restrict__ dst, const float* __restrict__ w) {
    int e = blockIdx.x * 256 + threadIdx.x;
    if (e < EE) atomicAdd(&g_degsp[dst[e]], w[e]);
}
__global__ void k_dinvsp() {
    int i = blockIdx.x * 256 + threadIdx.x;
    if (i < TWO_N) {
        float d = g_degsp[i];
        g_dinvsp[i] = d > 0.f ? rsqrtf(fmaxf(d, 1e-12f)) : 0.f;
    }
}
__global__ void k_count(const int* __restrict__ dst) {
    int e = blockIdx.x * 256 + threadIdx.x;
    if (e < EE) atomicAdd(&g_csr_cnt[dst[e]], 1);
}
// single block of 1024 threads, 6 counts per thread -> exclusive scan
__global__ void k_scan() {
    __shared__ int sh[1024];
    int tid = threadIdx.x;
    int base = tid * 6;
    int loc[6];
    int s = 0;
    #pragma unroll
    for (int k = 0; k < 6; k++) { loc[k] = s; s += g_csr_cnt[base + k]; }
    sh[tid] = s;
    __syncthreads();
    for (int off = 1; off < 1024; off <<= 1) {
        int add = (tid >= off) ? sh[tid - off] : 0;
        __syncthreads();
        sh[tid] += add;
        __syncthreads();
    }
    int excl = sh[tid] - s;
    #pragma unroll
    for (int k = 0; k < 6; k++) {
        int o = excl + loc[k];
        g_csr_off[base + k] = o;
        g_csr_cnt[base + k] = o;   // cursor for fill
    }
    if (tid == 1023) g_csr_off[TWO_N] = sh[1023];
}
__global__ void k_fillcsr(const int* __restrict__ src, const int* __restrict__ dst,
                          const float* __restrict__ w) {
    int e = blockIdx.x * 256 + threadIdx.x;
    if (e >= EE) return;
    int s = src[e], q = dst[e];
    int pos = atomicAdd(&g_csr_cnt[q], 1);
    g_csr_src[pos] = s;
    g_csr_coef[pos] = g_dinvsp[s] * g_dinvsp[q] * w[e];
}
// gather: one block per node, fuses self-loop + aggregation + bias + preserve blend
__global__ void k_spgather(const float* __restrict__ prev, float* __restrict__ dstb,
                           const float* __restrict__ b1, int layer) {
    int q = blockIdx.x;
    int t = threadIdx.x;  // 128
    float dv = g_dinvsp[q];
    float acc = dv * dv * g_xw[(size_t)q * DIM + t];
    int beg = g_csr_off[q], end = g_csr_off[q + 1];
    int j = beg;
    for (; j + 1 < end; j += 2) {
        float c0 = g_csr_coef[j],     c1 = g_csr_coef[j + 1];
        int   s0 = g_csr_src[j],      s1 = g_csr_src[j + 1];
        float x0 = g_xw[(size_t)s0 * DIM + t];
        float x1 = g_xw[(size_t)s1 * DIM + t];
        acc += c0 * x0 + c1 * x1;
    }
    if (j < end) acc += g_csr_coef[j] * g_xw[(size_t)g_csr_src[j] * DIM + t];
    float outv = acc + b1[layer * DIM + t];
    dstb[(size_t)q * DIM + t] = (1.f - PRESERVE) * outv + PRESERVE * prev[(size_t)q * DIM + t];
}

__global__ void k_addemb() {
    int i = blockIdx.x * 256 + threadIdx.x;
    if (i < TWO_N * DIM) g_emb[i] = g_tmpA[i] + g_tmpB[i];
}

// ----------------------------- pooling assignment softmax + entropy -----------------------------
__global__ void k_softmax_s() {
    int r = blockIdx.x, t = threadIdx.x;  // 128 threads
    __shared__ float sh[128];
    float v = (t < CC) ? g_sm[(size_t)r * CC + t] : -1e30f;
    float mx = blockReduceMax(v, sh);
    float e = (t < CC) ? expf(v - mx) : 0.f;
    float sum = blockReduceSum(e, sh);
    float p = e / sum;
    float ent = (t < CC) ? (-p * logf(p + 1e-15f)) : 0.f;
    float es = blockReduceSum(ent, sh);
    if (t < CC) g_sm[(size_t)r * CC + t] = p;
    if (t == 0) atomicAdd(&g_acc[2], es);
}

__global__ void k_pooled() {   // pooled[c,d] = sum_i s[i,c]*emb[i,d]
    int c4 = blockIdx.x * 4;
    int i0 = blockIdx.y * 768;
    int t = threadIdx.x;  // 128
    float acc[4] = {0.f, 0.f, 0.f, 0.f};
    for (int i = i0; i < i0 + 768; i++) {
        float ev = g_emb[(size_t)i * DIM + t];
        #pragma unroll
        for (int cc = 0; cc < 4; cc++)
            acc[cc] += g_sm[(size_t)i * CC + c4 + cc] * ev;
    }
    #pragma unroll
    for (int cc = 0; cc < 4; cc++)
        atomicAdd(&g_pooled[(size_t)(c4 + cc) * DIM + t], acc[cc]);
}

// ----------------------------- link loss pieces -----------------------------
__global__ void k_scatterA(const int* __restrict__ src, const int* __restrict__ dst,
                           const float* __restrict__ w) {
    int e = blockIdx.x * 256 + threadIdx.x;
    if (e < EE) atomicAdd(&g_Adense[(size_t)src[e] * TWO_N + dst[e]], w[e]);
}
__global__ void k_normA(const int* __restrict__ src, const int* __restrict__ dst) {
    __shared__ float sh[256];
    int e = blockIdx.x * 256 + threadIdx.x;
    float v = 0.f;
    if (e < EE) {
        float old = atomicExch(&g_Adense[(size_t)src[e] * TWO_N + dst[e]], 0.f);
        v = old * old;
    }
    float s = blockReduceSum(v, sh);
    if (threadIdx.x == 0 && s != 0.f) atomicAdd(&g_acc[0], s);
}
__global__ void k_cross(const int* __restrict__ src, const int* __restrict__ dst,
                        const float* __restrict__ w) {
    __shared__ float sh[8];
    int warp = threadIdx.x >> 5, lane = threadIdx.x & 31;
    int e = blockIdx.x * 8 + warp;
    float acc = 0.f;
    if (e < EE) {
        int s = src[e], q = dst[e];
        for (int c = lane; c < CC; c += 32)
            acc += g_sm[(size_t)s * CC + c] * g_sm[(size_t)q * CC + c];
        acc *= w[e];
    }
    for (int o = 16; o > 0; o >>= 1) acc += __shfl_down_sync(0xffffffff, acc, o);
    if (lane == 0) sh[warp] = acc;
    __syncthreads();
    if (threadIdx.x == 0) {
        float s = 0.f;
        for (int i = 0; i < 8; i++) s += sh[i];
        atomicAdd(&g_acc[1], s);
    }
}
__global__ void k_gram() {   // G[c,c'] += sum_{i in chunk} s[i,c]*s[i,c']
    int c = blockIdx.x;
    int i0 = blockIdx.y * 768;
    int t = threadIdx.x;  // 128
    if (t >= CC) return;
    float acc = 0.f;
    for (int i = i0; i < i0 + 768; i++) {
        float sc = g_sm[(size_t)i * CC + c];
        acc += sc * g_sm[(size_t)i * CC + t];
    }
    atomicAdd(&g_G[c * CC + t], acc);
}
__global__ void k_gramsq() {
    __shared__ float sh[256];
    int t = threadIdx.x;
    float acc = 0.f;
    for (int i = t; i < CC * CC; i += 256) { float g = g_G[i]; acc += g * g; }
    float s = blockReduceSum(acc, sh);
    if (t == 0) g_acc[3] = s;
}
__global__ void k_finalize(float* __restrict__ out_loss) {
    float n2 = g_acc[0] - 2.f * g_acc[1] + g_acc[3];
    float link = sqrtf(fmaxf(n2, 0.f)) / ((float)TWO_N * (float)TWO_N);
    out_loss[0] = link + g_acc[2] / (float)TWO_N;
}

// ----------------------------- MHA2 -----------------------------
__global__ void k_transpose128(const float* __restrict__ wi) {  // g_wt[k,n] = wi[n,k]
    int idx = blockIdx.x * 256 + threadIdx.x;
    if (idx >= DIM * DIM) return;
    int n = idx >> 7, k = idx & 127;
    g_wt[(size_t)k * DIM + n] = wi[(size_t)n * DIM + k];
}
__global__ void k_kvproj(const float* __restrict__ wi, const float* __restrict__ bi) {
    int c = blockIdx.x;       // pooled row
    int which = blockIdx.y;   // 0=K, 1=V
    int t = threadIdx.x;      // 128
    __shared__ float prow[DIM];
    prow[t] = g_pooled[(size_t)c * DIM + t];
    __syncthreads();
    const float4* row4 = reinterpret_cast<const float4*>(wi + (size_t)(DIM + which * DIM + t) * DIM);
    float acc = bi[DIM + which * DIM + t];
    #pragma unroll
    for (int k = 0; k < 32; k++) {
        float4 r = row4[k];
        acc += r.x * prow[4 * k] + r.y * prow[4 * k + 1]
             + r.z * prow[4 * k + 2] + r.w * prow[4 * k + 3];
    }
    (which ? g_vp2 : g_kp2)[(size_t)c * DIM + t] = acc;
}

#define K_LD 129
// K staged in smem (51.6KB -> 4 blocks/SM); V read from L1/L2; warp-per-head softmax.
__global__ void k_mha2(const float* __restrict__ wo, const float* __restrict__ bo,
                       float* __restrict__ out_skill) {
    extern __shared__ float kp_s[];     // [CC][K_LD]
    __shared__ float qrow[DIM];
    __shared__ float lg[HH][CC];
    __shared__ float o_s[DIM];
    int t = threadIdx.x;  // 128
    int w = t >> 5, lane = t & 31;
    for (int i = t; i < CC * DIM; i += 128) {
        int j = i >> 7, d = i & 127;
        kp_s[j * K_LD + d] = g_kp2[i];
    }
    __syncthreads();
    int n0 = blockIdx.x * 16;
    for (int q = 0; q < 16; q++) {
        int n = n0 + q;
        qrow[t] = g_qp2[(size_t)n * DIM + t];
        __syncthreads();
        for (int pos = t; pos < HH * CC; pos += 128) {
            int h = pos / CC, j = pos % CC;
            float acc = 0.f;
            #pragma unroll 8
            for (int d = 0; d < HD; d++)
                acc += qrow[h * HD + d] * kp_s[j * K_LD + h * HD + d];
            lg[h][j] = acc * INV_SQRT_HD;
        }
        __syncthreads();
        {   // warp w handles head w softmax over CC
            float mx = -1e30f;
            for (int j = lane; j < CC; j += 32) mx = fmaxf(mx, lg[w][j]);
            #pragma unroll
            for (int o = 16; o > 0; o >>= 1) mx = fmaxf(mx, __shfl_xor_sync(0xffffffff, mx, o));
            float sm = 0.f;
            for (int j = lane; j < CC; j += 32) { float e = expf(lg[w][j] - mx); lg[w][j] = e; sm += e; }
            #pragma unroll
            for (int o = 16; o > 0; o >>= 1) sm += __shfl_xor_sync(0xffffffff, sm, o);
            float inv = 1.f / sm;
            for (int j = lane; j < CC; j += 32) lg[w][j] *= inv;
        }
        __syncthreads();
        {   // ctx: o_s[t] = sum_j p[h(t)][j] * V[j][t]
            float acc = 0.f;
            for (int j = 0; j < CC; j++) acc += lg[w][j] * g_vp2[(size_t)j * DIM + t];
            o_s[t] = acc;
        }
        __syncthreads();
        {   // out proj (float4) + residuals
            const float4* row4 = reinterpret_cast<const float4*>(wo + (size_t)t * DIM);
            float acc = bo[t];
            #pragma unroll
            for (int k = 0; k < 32; k++) {
                float4 r = row4[k];
                acc += r.x * o_s[4 * k] + r.y * o_s[4 * k + 1]
                     + r.z * o_s[4 * k + 2] + r.w * o_s[4 * k + 3];
            }
            out_skill[(size_t)n * DIM + t] = 2.f * g_emb[(size_t)n * DIM + t] + acc;
        }
        __syncthreads();
    }
}

// ----------------------------- host launch -----------------------------
extern "C" void kernel_launch(void* const* d_in, const int* in_sizes, int n_in,
                              void* d_out, int out_size) {
    const float* demand = (const float*)d_in[0];
    const float* supply = (const float*)d_in[1];
    const float* skill  = (const float*)d_in[2];
    const int*   eidx   = (const int*)d_in[3];
    const float* eattr  = (const float*)d_in[4];
    const float* w_fuse = (const float*)d_in[5];
    const float* b_fuse = (const float*)d_in[6];
    const float* m1wi   = (const float*)d_in[7];
    const float* m1bi   = (const float*)d_in[8];
    const float* m1wo   = (const float*)d_in[9];
    const float* m1bo   = (const float*)d_in[10];
    const float* m2wi   = (const float*)d_in[11];
    const float* m2bi   = (const float*)d_in[12];
    const float* m2wo   = (const float*)d_in[13];
    const float* m2bo   = (const float*)d_in[14];
    const float* sender = (const float*)d_in[15];
    const float* recv   = (const float*)d_in[16];
    const float* W0     = (const float*)d_in[17];
    const float* b0     = (const float*)d_in[18];
    const float* W1     = (const float*)d_in[19];
    const float* b1     = (const float*)d_in[20];
    const float* Wp     = (const float*)d_in[21];
    const float* bp     = (const float*)d_in[22];
    float* out = (float*)d_out;
    const int* src = eidx;
    const int* dst = eidx + EE;

    cudaFuncSetAttribute(k_mha2, cudaFuncAttributeMaxDynamicSharedMemorySize,
                         CC * K_LD * (int)sizeof(float) + 1024);

    float *p_cat2, *p_fused, *p_xw, *p_tmpA, *p_tmpB, *p_emb, *p_sm, *p_wt, *p_qp2;
    cudaGetSymbolAddress((void**)&p_cat2, g_cat2);
    cudaGetSymbolAddress((void**)&p_fused, g_fused);
    cudaGetSymbolAddress((void**)&p_xw, g_xw);
    cudaGetSymbolAddress((void**)&p_tmpA, g_tmpA);
    cudaGetSymbolAddress((void**)&p_tmpB, g_tmpB);
    cudaGetSymbolAddress((void**)&p_emb, g_emb);
    cudaGetSymbolAddress((void**)&p_sm, g_sm);
    cudaGetSymbolAddress((void**)&p_wt, g_wt);
    cudaGetSymbolAddress((void**)&p_qp2, g_qp2);

    k_init<<<64, 256>>>(sender, recv);
    k_seqsum<<<dim3(2, 24), 128>>>(demand, supply);
    k_seqsum2<<<2, 128>>>();
    k_mha1<<<TWO_N, 128>>>(demand, supply, skill, m1wi, m1bi, m1wo, m1bo);
    k_cat2<<<TWO_N, 128>>>(skill, out + OUT_CAT);
    k_sgemm<<<dim3(1, TWO_N / 64), 256>>>(p_cat2, w_fuse, b_fuse, p_fused, TWO_N, DIM, 2 * DIM, DIM);
    k_tanhprep<<<TWO_N * DIM / 256, 256>>>(sender, recv);
    k_scores<<<dim3(TWO_N / 16, TWO_N / 16), 256>>>();
    k_predg<<<TWO_N, 256>>>(out + OUT_PRED);
    k_dinv<<<24, 256>>>();

    // dense GCN (2 layers)
    for (int l = 0; l < 2; l++) {
        const float* srcbuf = (l == 0) ? p_fused : p_tmpA;
        k_sgemm<<<dim3(1, TWO_N / 64), 256>>>(srcbuf, W0 + (size_t)l * DIM * DIM, nullptr, p_xw,
                                              TWO_N, DIM, DIM, DIM);
        k_scale_rows<<<TWO_N * DIM / 256, 256>>>();
        k_dense_agg<<<TWO_N / 32, 256>>>();
        k_dense_combine<<<TWO_N * DIM / 256, 256>>>(srcbuf, p_tmpA, b0, l);
    }

    // sparse GCN: CSR build once, then 2 gather layers
    k_degsp<<<EE / 256, 256>>>(dst, eattr);
    k_dinvsp<<<24, 256>>>();
    k_count<<<EE / 256, 256>>>(dst);
    k_scan<<<1, 1024>>>();
    k_fillcsr<<<EE / 256, 256>>>(src, dst, eattr);
    for (int l = 0; l < 2; l++) {
        const float* srcbuf = (l == 0) ? p_fused : p_tmpB;
        k_sgemm<<<dim3(1, TWO_N / 64), 256>>>(srcbuf, W1 + (size_t)l * DIM * DIM, nullptr, p_xw,
                                              TWO_N, DIM, DIM, DIM);
        k_spgather<<<TWO_N, 128>>>(srcbuf, p_tmpB, b1, l);
    }

    k_addemb<<<TWO_N * DIM / 256, 256>>>();

    // diff-pool
    k_sgemm<<<dim3(1, TWO_N / 64), 256>>>(p_emb, Wp, bp, p_sm, TWO_N, CC, DIM, CC);
    k_softmax_s<<<TWO_N, 128>>>();
    k_pooled<<<dim3(25, 8), 128>>>();
    k_scatterA<<<EE / 256, 256>>>(src, dst, eattr);
    k_cross<<<EE / 8, 256>>>(src, dst, eattr);
    k_normA<<<EE / 256, 256>>>(src, dst);
    k_gram<<<dim3(CC, 8), 128>>>();
    k_gramsq<<<1, 256>>>();
    k_finalize<<<1, 1>>>(out + OUT_LOSS);

    // MHA2
    k_transpose128<<<DIM * DIM / 256, 256>>>(m2wi);
    k_sgemm<<<dim3(1, TWO_N / 64), 256>>>(p_emb, p_wt, m2bi, p_qp2, TWO_N, DIM, DIM, DIM);
    k_kvproj<<<dim3(CC, 2), 128>>>(m2wi, m2bi);
    k_mha2<<<TWO_N / 16, 128, CC * K_LD * sizeof(float) + 1024>>>(m2wo, m2bo, out + OUT_SKILL);
}

// round 6
// speedup vs baseline: 2.8220x; 1.2176x over previous
#include <cuda_runtime.h>
#include <math.h>

#define NN      3072
#define TWO_N   6144
#define DIM     128
#define SEQ     16
#define EE      196608
#define CC      100
#define HH      4
#define HD      32
#define INV_SQRT_HD 0.17677669529663687f
#define DELTA_T 0.1f
#define PRESERVE 0.1f

#define OUT_CAT   0
#define OUT_SKILL (TWO_N * DIM)
#define OUT_PRED  (2 * TWO_N * DIM)
#define OUT_LOSS  (2 * TWO_N * DIM + TWO_N * TWO_N)

// ----------------------------- device scratch -----------------------------
__device__ float g_dsum[DIM];
__device__ float g_ssum[DIM];
__device__ float g_seqpart[2][24][DIM];
__device__ float g_seq_att[(size_t)TWO_N * DIM];
__device__ float g_cat2[(size_t)TWO_N * 2 * DIM];
__device__ float g_fused[(size_t)TWO_N * DIM];
__device__ float g_s1[(size_t)TWO_N * DIM];
__device__ float g_s2[(size_t)TWO_N * DIM];
__device__ float g_scores[(size_t)TWO_N * TWO_N];   // general path only
__device__ float g_Adense[(size_t)TWO_N * TWO_N];   // zero between launches (exch trick)
__device__ float g_deg[TWO_N];
__device__ float g_dinv[TWO_N];
__device__ float g_degsp[TWO_N];
__device__ float g_dinvsp[TWO_N];
__device__ float g_xw[(size_t)TWO_N * DIM];
__device__ float g_agg[(size_t)TWO_N * DIM];
__device__ float g_tmpA[(size_t)TWO_N * DIM];
__device__ float g_tmpB[(size_t)TWO_N * DIM];
__device__ float g_emb[(size_t)TWO_N * DIM];
__device__ float g_sm[(size_t)TWO_N * CC];
__device__ float g_pooled[CC * DIM];
__device__ float g_G[CC * CC];
__device__ float g_kp2[CC * DIM];
__device__ float g_vp2[CC * DIM];
__device__ float g_qp2[(size_t)TWO_N * DIM];
__device__ float g_wt[DIM * DIM];
__device__ float g_acc[8];   // [0]=||A||^2 [1]=<A,SS^T> [2]=ent_sum [3]=||S^T S||^2
__device__ int   g_flag;     // 1 if sender == receiver -> scores == 0 exactly

// MHA1 GEMM-chain buffers
__device__ float g_qv[(size_t)TWO_N * DIM];
__device__ float g_qp1[(size_t)TWO_N * DIM];
__device__ float g_U[(size_t)TWO_N * 4 * DIM];   // [2N, 512]
__device__ float g_c[(size_t)TWO_N * 4 * DIM];   // [2N, 512]
__device__ float g_wqt[DIM * DIM];
__device__ float g_Mk[DIM * 4 * DIM];            // [128, 512]
__device__ float g_Zcat[4 * DIM * DIM];          // [512, 128]
__device__ float g_zb[DIM];

// CSR for sparse GCN (gather form)
__device__ int   g_csr_cnt[TWO_N];      // counts, then cursors
__device__ int   g_csr_off[TWO_N + 1];
__device__ int   g_csr_src[EE];
__device__ float g_csr_coef[EE];

// ----------------------------- helpers -----------------------------
__device__ __forceinline__ float blockReduceSum(float v, float* sh) {
    int t = threadIdx.x;
    sh[t] = v; __syncthreads();
    for (int s = blockDim.x >> 1; s > 0; s >>= 1) {
        if (t < s) sh[t] += sh[t + s];
        __syncthreads();
    }
    float r = sh[0]; __syncthreads();
    return r;
}
__device__ __forceinline__ float blockReduceMax(float v, float* sh) {
    int t = threadIdx.x;
    sh[t] = v; __syncthreads();
    for (int s = blockDim.x >> 1; s > 0; s >>= 1) {
        if (t < s) sh[t] = fmaxf(sh[t], sh[t + s]);
        __syncthreads();
    }
    float r = sh[0]; __syncthreads();
    return r;
}

// ----------------------------- init -----------------------------
__global__ void k_init(const float* __restrict__ sender, const float* __restrict__ receiver) {
    int i = blockIdx.x * blockDim.x + threadIdx.x;
    if (i < TWO_N) { g_deg[i] = 1.0f; g_degsp[i] = 1.0f; g_csr_cnt[i] = 0; }
    if (i < CC * DIM) g_pooled[i] = 0.f;
    if (i < CC * CC) g_G[i] = 0.f;
    if (i < 8) g_acc[i] = 0.f;
    if (i == 0) g_flag = (sender[0] == receiver[0]) ? 1 : 0;
}

// ----------------------------- seq last-step sums -----------------------------
__global__ void k_seqsum(const float* __restrict__ demand, const float* __restrict__ supply) {
    int tensor = blockIdx.x, chunk = blockIdx.y, d = threadIdx.x;
    const float* base = tensor ? supply : demand;
    float acc = 0.f;
    int n0 = chunk * 128;
    for (int n = n0; n < n0 + 128; n++)
        acc += base[(size_t)n * SEQ * DIM + (size_t)(SEQ - 1) * DIM + d];
    g_seqpart[tensor][chunk][d] = acc;
}
__global__ void k_seqsum2() {
    int tensor = blockIdx.x, d = threadIdx.x;
    float acc = 0.f;
    for (int c = 0; c < 24; c++) acc += g_seqpart[tensor][c][d];
    (tensor ? g_ssum : g_dsum)[d] = acc;
}

// ----------------------------- MHA1 weight precompute (tiny, once/launch) -----------------------------
__global__ void k_wqt(const float* __restrict__ wi) {   // WqT[k,t] = Wq[t,k]
    int i = blockIdx.x * 256 + threadIdx.x;
    if (i >= DIM * DIM) return;
    int k = i >> 7, t = i & 127;
    g_wqt[i] = wi[(size_t)t * DIM + k];
}
__global__ void k_mk(const float* __restrict__ wi) {    // Mk[j, h*128+d] = (j in head h)? Wk[j,d] : 0
    int i = blockIdx.x * 256 + threadIdx.x;
    if (i >= DIM * 4 * DIM) return;
    int j = i >> 9, col = i & 511;
    int h = col >> 7, d = col & 127;
    const float* wk = wi + (size_t)DIM * DIM;
    g_Mk[i] = ((j >> 5) == h) ? wk[(size_t)j * DIM + d] : 0.f;
}
__global__ void k_zcat(const float* __restrict__ wi, const float* __restrict__ wo) {
    // Zcat[h*128+d, t] = sum_j Wo[t, h*32+j] * Wv[h*32+j, d]
    int row = blockIdx.x;   // 0..511
    int t = threadIdx.x;    // 128
    int h = row >> 7, d = row & 127;
    const float* wv = wi + (size_t)2 * DIM * DIM;
    float acc = 0.f;
    #pragma unroll 8
    for (int j = 0; j < 32; j++)
        acc += wo[(size_t)t * DIM + h * 32 + j] * wv[(size_t)(h * 32 + j) * DIM + d];
    g_Zcat[(size_t)row * DIM + t] = acc;
}
__global__ void k_zb(const float* __restrict__ wo, const float* __restrict__ bo,
                     const float* __restrict__ bi) {
    int t = threadIdx.x;
    const float* bv = bi + 2 * DIM;
    float acc = bo[t];
    #pragma unroll 8
    for (int k = 0; k < DIM; k++) acc += wo[(size_t)t * DIM + k] * bv[k];
    g_zb[t] = acc;
}
__global__ void k_qv(const float* __restrict__ skill) {
    int i = blockIdx.x * 256 + threadIdx.x;
    if (i >= TWO_N * DIM) return;
    int b = i >> 7, t = i & 127;
    bool dem = b < NN;
    int idx = dem ? b : b - NN;
    g_qv[i] = skill[(size_t)idx * DIM + t] + (dem ? g_dsum : g_ssum)[t];
}

// ----------------------------- MHA1 attention core (per batch row) -----------------------------
__global__ void k_attn1(const float* __restrict__ demand, const float* __restrict__ supply,
                        const float* __restrict__ bi) {
    int b = blockIdx.x;
    int t = threadIdx.x;  // 128
    int w = t >> 5, lane = t & 31;
    bool dem = b < NN;
    int idx = dem ? b : b - NN;
    const float* seq = (dem ? demand : supply) + (size_t)idx * SEQ * DIM;

    __shared__ float sh_seq[SEQ][DIM + 1];
    __shared__ float sh_U[HH][DIM];
    __shared__ float sh_p[HH][SEQ];

    for (int i = t; i < SEQ * DIM; i += 128) sh_seq[i >> 7][i & 127] = seq[i];
    for (int i = t; i < HH * DIM; i += 128) sh_U[i >> 7][i & 127] = g_U[(size_t)b * 512 + i];
    __syncthreads();

    // qb[h] = dot(qp[b, h-slice], bk[h-slice])  (warp w = head w)
    const float* bk = bi + DIM;
    float qb = g_qp1[(size_t)b * DIM + w * HD + lane] * bk[w * HD + lane];
    #pragma unroll
    for (int o = 16; o > 0; o >>= 1) qb += __shfl_xor_sync(0xffffffff, qb, o);

    // logits: lane s<16 computes l[w][s]
    float myl = -1e30f;
    if (lane < SEQ) {
        float acc = 0.f;
        #pragma unroll 16
        for (int d = 0; d < DIM; d++) acc += sh_U[w][d] * sh_seq[lane][d];
        myl = (acc + qb) * INV_SQRT_HD;
    }
    // softmax over 16 lanes (lanes >=16 hold -inf / 0)
    float mx = myl;
    #pragma unroll
    for (int o = 8; o > 0; o >>= 1) mx = fmaxf(mx, __shfl_xor_sync(0xffffffff, mx, o));
    float e = (lane < SEQ) ? expf(myl - mx) : 0.f;
    float sm = e;
    #pragma unroll
    for (int o = 8; o > 0; o >>= 1) sm += __shfl_xor_sync(0xffffffff, sm, o);
    if (lane < SEQ) sh_p[w][lane] = e / sm;
    __syncthreads();

    // ctx: c[b, w*128 + d] = sum_s p[w][s] seq[s][d]
    #pragma unroll
    for (int k = 0; k < 4; k++) {
        int d = lane + 32 * k;
        float acc = 0.f;
        #pragma unroll
        for (int s = 0; s < SEQ; s++) acc += sh_p[w][s] * sh_seq[s][d];
        g_c[(size_t)b * 512 + w * DIM + d] = acc;
    }
}

// ----------------------------- concat builder + cat output -----------------------------
__global__ void k_cat2(const float* __restrict__ skill, float* __restrict__ out_cat) {
    int r = blockIdx.x, t = threadIdx.x;
    int idx = r < NN ? r : r - NN;
    float sv = skill[(size_t)idx * DIM + t];
    g_cat2[(size_t)r * 2 * DIM + t] = sv;
    g_cat2[(size_t)r * 2 * DIM + DIM + t] = g_seq_att[(size_t)r * DIM + t];
    out_cat[(size_t)r * DIM + t] = sv;
}

// ----------------------------- generic SGEMM: C = A[MxK] @ B[KxN] (+bias) -----------------------------
__global__ void k_sgemm(const float* __restrict__ A, const float* __restrict__ B,
                        const float* __restrict__ bias, float* __restrict__ Cmat,
                        int M, int Nn, int K, int ldc) {
    const int BM = 64, BN = 128, BK = 16;
    __shared__ float As[BK][BM];
    __shared__ float Bs[BK][BN];
    int bm = blockIdx.y * BM;
    int bn = blockIdx.x * BN;
    int tid = threadIdx.x;
    int tr = tid >> 4;
    int tc = tid & 15;
    float acc[4][8];
    #pragma unroll
    for (int r = 0; r < 4; r++)
        #pragma unroll
        for (int c = 0; c < 8; c++) acc[r][c] = 0.f;

    for (int k0 = 0; k0 < K; k0 += BK) {
        #pragma unroll
        for (int j = 0; j < 4; j++) {
            int idx = tid + 256 * j;
            int m = idx >> 4, kk = idx & 15;
            As[kk][m] = A[(size_t)(bm + m) * K + k0 + kk];
        }
        #pragma unroll
        for (int j = 0; j < 8; j++) {
            int idx = tid + 256 * j;
            int kk = idx >> 7, n = idx & 127;
            float v = 0.f;
            if (bn + n < Nn) v = B[(size_t)(k0 + kk) * Nn + bn + n];
            Bs[kk][n] = v;
        }
        __syncthreads();
        #pragma unroll
        for (int kk = 0; kk < BK; kk++) {
            float a[4], bb[8];
            #pragma unroll
            for (int r = 0; r < 4; r++) a[r] = As[kk][tr * 4 + r];
            #pragma unroll
            for (int c = 0; c < 8; c++) bb[c] = Bs[kk][tc * 8 + c];
            #pragma unroll
            for (int r = 0; r < 4; r++)
                #pragma unroll
                for (int c = 0; c < 8; c++) acc[r][c] += a[r] * bb[c];
        }
        __syncthreads();
    }
    #pragma unroll
    for (int r = 0; r < 4; r++) {
        int m = bm + tr * 4 + r;
        if (m >= M) continue;
        #pragma unroll
        for (int c = 0; c < 8; c++) {
            int n = bn + tc * 8 + c;
            if (n < Nn) {
                float v = acc[r][c];
                if (bias) v += bias[n];
                Cmat[(size_t)m * ldc + n] = v;
            }
        }
    }
}

// ----------------------------- tanh prep -----------------------------
__global__ void k_tanhprep(const float* __restrict__ sender, const float* __restrict__ receiver) {
    int i = blockIdx.x * 256 + threadIdx.x;
    if (i >= TWO_N * DIM) return;
    float f = g_fused[i];
    g_s1[i] = tanhf(sender[0] * f);
    g_s2[i] = tanhf(receiver[0] * f);
}

// ----------------------------- scores (general path only; grid-stride, skipped when flag) -------------
__global__ void k_scores() {
    if (g_flag) return;
    __shared__ float A1[16][DIM], A2[16][DIM], B1[16][DIM], B2[16][DIM];
    int t = threadIdx.x;  // 256
    const int TILES = TWO_N / 16;
    for (int tile = blockIdx.x; tile < TILES * TILES; tile += gridDim.x) {
        int i0 = (tile / TILES) * 16, j0 = (tile % TILES) * 16;
        __syncthreads();
        for (int j = 0; j < 8; j++) {
            int idx = t + 256 * j;           // 0..2047
            int r = idx >> 7, c = idx & 127;
            A1[r][c] = g_s1[(size_t)(i0 + r) * DIM + c];
            A2[r][c] = g_s2[(size_t)(i0 + r) * DIM + c];
            B1[r][c] = g_s1[(size_t)(j0 + r) * DIM + c];
            B2[r][c] = g_s2[(size_t)(j0 + r) * DIM + c];
        }
        __syncthreads();
        int ti = t >> 4, tj = t & 15;
        float acc = 0.f;
        for (int k = 0; k < DIM; k++)
            acc += A1[ti][k] * B2[tj][k] - A2[ti][k] * B1[tj][k];
        g_scores[(size_t)(i0 + ti) * TWO_N + j0 + tj] = acc;
    }
}

// ----------------------------- row softmax -> pred_g (+ col-deg), or zero-fill -----------------------------
__global__ void k_predg(float* __restrict__ out_pred) {
    int row = blockIdx.x;
    int t = threadIdx.x;  // 256
    __shared__ float sh[256];
    float4* outr = reinterpret_cast<float4*>(out_pred + (size_t)row * TWO_N);
    if (g_flag) {
        float4 z = make_float4(0.f, 0.f, 0.f, 0.f);
        for (int i = t; i < TWO_N / 4; i += 256) outr[i] = z;
        return;
    }
    float* sr = g_scores + (size_t)row * TWO_N;
    float mx = 0.f;  // relu'd values >= 0
    for (int i = t; i < TWO_N; i += 256) mx = fmaxf(mx, fmaxf(sr[i], 0.f));
    mx = blockReduceMax(mx, sh);
    float sum = 0.f;
    for (int i = t; i < TWO_N; i += 256) sum += expf(fmaxf(sr[i], 0.f) - mx);
    sum = blockReduceSum(sum, sh);
    float inv = 1.f / sum;
    for (int i = t; i < TWO_N; i += 256) {
        float p = expf(fmaxf(sr[i], 0.f) - mx) * inv;
        float pr = fmaxf(p - DELTA_T, 0.f);
        sr[i] = pr;
        out_pred[(size_t)row * TWO_N + i] = pr;
        if (pr != 0.f) atomicAdd(&g_deg[i], pr);
    }
}

__global__ void k_dinv() {
    int i = blockIdx.x * 256 + threadIdx.x;
    if (i < TWO_N) g_dinv[i] = rsqrtf(g_deg[i]);
}

// ----------------------------- dense GCN pieces -----------------------------
__global__ void k_scale_rows() {   // xw[i,:] *= dinv[i]
    int i = blockIdx.x * 256 + threadIdx.x;
    if (i >= TWO_N * DIM) return;
    g_xw[i] *= g_dinv[i >> 7];
}

__global__ void k_dense_agg() {    // general path: agg = pred^T @ xws + xws
    if (g_flag) return;
    int i0 = blockIdx.x * 32;
    int t = threadIdx.x;  // 256
    __shared__ float pcol[32];
    __shared__ float xrow[DIM];
    int dbase = t & 127, half = t >> 7;  // half in {0,1}
    float acc[16];
    #pragma unroll
    for (int r = 0; r < 16; r++) acc[r] = 0.f;
    for (int j = 0; j < TWO_N; j++) {
        if (t < 32) pcol[t] = g_scores[(size_t)j * TWO_N + i0 + t];
        else if (t >= 128 && t < 256) xrow[t - 128] = g_xw[(size_t)j * DIM + (t - 128)];
        __syncthreads();
        #pragma unroll
        for (int r = 0; r < 16; r++) acc[r] += pcol[half + 2 * r] * xrow[dbase];
        __syncthreads();
    }
    #pragma unroll
    for (int r = 0; r < 16; r++) {
        int i = i0 + half + 2 * r;
        g_agg[(size_t)i * DIM + dbase] = acc[r] + g_xw[(size_t)i * DIM + dbase];
    }
}

__global__ void k_dense_combine(const float* __restrict__ prev, float* __restrict__ dst,
                                const float* __restrict__ b0, int layer) {
    int i = blockIdx.x * 256 + threadIdx.x;
    if (i >= TWO_N * DIM) return;
    float v = g_flag ? g_xw[i] : g_agg[i];
    float out = g_dinv[i >> 7] * v + b0[layer * DIM + (i & 127)];
    dst[i] = (1.f - PRESERVE) * out + PRESERVE * prev[i];
}

// ----------------------------- sparse GCN: CSR build + gather -----------------------------
__global__ void k_degsp(const int* __restrict__ dst, const float* __restrict__ w) {
    int e = blockIdx.x * 256 + threadIdx.x;
    if (e < EE) atomicAdd(&g_degsp[dst[e]], w[e]);
}
__global__ void k_dinvsp() {
    int i = blockIdx.x * 256 + threadIdx.x;
    if (i < TWO_N) {
        float d = g_degsp[i];
        g_dinvsp[i] = d > 0.f ? rsqrtf(fmaxf(d, 1e-12f)) : 0.f;
    }
}
__global__ void k_count(const int* __restrict__ dst) {
    int e = blockIdx.x * 256 + threadIdx.x;
    if (e < EE) atomicAdd(&g_csr_cnt[dst[e]], 1);
}
// single block of 1024 threads, 6 counts per thread -> exclusive scan
__global__ void k_scan() {
    __shared__ int sh[1024];
    int tid = threadIdx.x;
    int base = tid * 6;
    int loc[6];
    int s = 0;
    #pragma unroll
    for (int k = 0; k < 6; k++) { loc[k] = s; s += g_csr_cnt[base + k]; }
    sh[tid] = s;
    __syncthreads();
    for (int off = 1; off < 1024; off <<= 1) {
        int add = (tid >= off) ? sh[tid - off] : 0;
        __syncthreads();
        sh[tid] += add;
        __syncthreads();
    }
    int excl = sh[tid] - s;
    #pragma unroll
    for (int k = 0; k < 6; k++) {
        int o = excl + loc[k];
        g_csr_off[base + k] = o;
        g_csr_cnt[base + k] = o;   // cursor for fill
    }
    if (tid == 1023) g_csr_off[TWO_N] = sh[1023];
}
__global__ void k_fillcsr(const int* __restrict__ src, const int* __restrict__ dst,
                          const float* __restrict__ w) {
    int e = blockIdx.x * 256 + threadIdx.x;
    if (e >= EE) return;
    int s = src[e], q = dst[e];
    int pos = atomicAdd(&g_csr_cnt[q], 1);
    g_csr_src[pos] = s;
    g_csr_coef[pos] = g_dinvsp[s] * g_dinvsp[q] * w[e];
}
// gather: one block per node, fuses self-loop + aggregation + bias + preserve blend
__global__ void k_spgather(const float* __restrict__ prev, float* __restrict__ dstb,
                           const float* __restrict__ b1, int layer) {
    int q = blockIdx.x;
    int t = threadIdx.x;  // 128
    float dv = g_dinvsp[q];
    float acc = dv * dv * g_xw[(size_t)q * DIM + t];
    int beg = g_csr_off[q], end = g_csr_off[q + 1];
    int j = beg;
    for (; j + 1 < end; j += 2) {
        float c0 = g_csr_coef[j],     c1 = g_csr_coef[j + 1];
        int   s0 = g_csr_src[j],      s1 = g_csr_src[j + 1];
        float x0 = g_xw[(size_t)s0 * DIM + t];
        float x1 = g_xw[(size_t)s1 * DIM + t];
        acc += c0 * x0 + c1 * x1;
    }
    if (j < end) acc += g_csr_coef[j] * g_xw[(size_t)g_csr_src[j] * DIM + t];
    float outv = acc + b1[layer * DIM + t];
    dstb[(size_t)q * DIM + t] = (1.f - PRESERVE) * outv + PRESERVE * prev[(size_t)q * DIM + t];
}

__global__ void k_addemb() {
    int i = blockIdx.x * 256 + threadIdx.x;
    if (i < TWO_N * DIM) g_emb[i] = g_tmpA[i] + g_tmpB[i];
}

// ----------------------------- pooling assignment softmax + entropy -----------------------------
__global__ void k_softmax_s() {
    int r = blockIdx.x, t = threadIdx.x;  // 128 threads
    __shared__ float sh[128];
    float v = (t < CC) ? g_sm[(size_t)r * CC + t] : -1e30f;
    float mx = blockReduceMax(v, sh);
    float e = (t < CC) ? expf(v - mx) : 0.f;
    float sum = blockReduceSum(e, sh);
    float p = e / sum;
    float ent = (t < CC) ? (-p * logf(p + 1e-15f)) : 0.f;
    float es = blockReduceSum(ent, sh);
    if (t < CC) g_sm[(size_t)r * CC + t] = p;
    if (t == 0) atomicAdd(&g_acc[2], es);
}

__global__ void k_pooled() {   // pooled[c,d] = sum_i s[i,c]*emb[i,d]
    int c4 = blockIdx.x * 4;
    int i0 = blockIdx.y * 768;
    int t = threadIdx.x;  // 128
    float acc[4] = {0.f, 0.f, 0.f, 0.f};
    for (int i = i0; i < i0 + 768; i++) {
        float ev = g_emb[(size_t)i * DIM + t];
        #pragma unroll
        for (int cc = 0; cc < 4; cc++)
            acc[cc] += g_sm[(size_t)i * CC + c4 + cc] * ev;
    }
    #pragma unroll
    for (int cc = 0; cc < 4; cc++)
        atomicAdd(&g_pooled[(size_t)(c4 + cc) * DIM + t], acc[cc]);
}

// ----------------------------- link loss pieces -----------------------------
__global__ void k_scatterA(const int* __restrict__ src, const int* __restrict__ dst,
                           const float* __restrict__ w) {
    int e = blockIdx.x * 256 + threadIdx.x;
    if (e < EE) atomicAdd(&g_Adense[(size_t)src[e] * TWO_N + dst[e]], w[e]);
}
__global__ void k_normA(const int* __restrict__ src, const int* __restrict__ dst) {
    __shared__ float sh[256];
    int e = blockIdx.x * 256 + threadIdx.x;
    float v = 0.f;
    if (e < EE) {
        float old = atomicExch(&g_Adense[(size_t)src[e] * TWO_N + dst[e]], 0.f);
        v = old * old;
    }
    float s = blockReduceSum(v, sh);
    if (threadIdx.x == 0 && s != 0.f) atomicAdd(&g_acc[0], s);
}
__global__ void k_cross(const int* __restrict__ src, const int* __restrict__ dst,
                        const float* __restrict__ w) {
    __shared__ float sh[8];
    int warp = threadIdx.x >> 5, lane = threadIdx.x & 31;
    int e = blockIdx.x * 8 + warp;
    float acc = 0.f;
    if (e < EE) {
        int s = src[e], q = dst[e];
        for (int c = lane; c < CC; c += 32)
            acc += g_sm[(size_t)s * CC + c] * g_sm[(size_t)q * CC + c];
        acc *= w[e];
    }
    for (int o = 16; o > 0; o >>= 1) acc += __shfl_down_sync(0xffffffff, acc, o);
    if (lane == 0) sh[warp] = acc;
    __syncthreads();
    if (threadIdx.x == 0) {
        float s = 0.f;
        for (int i = 0; i < 8; i++) s += sh[i];
        atomicAdd(&g_acc[1], s);
    }
}
__global__ void k_gram() {   // G[c,c'] += sum_{i in chunk} s[i,c]*s[i,c']
    int c = blockIdx.x;
    int i0 = blockIdx.y * 768;
    int t = threadIdx.x;  // 128
    if (t >= CC) return;
    float acc = 0.f;
    for (int i = i0; i < i0 + 768; i++) {
        float sc = g_sm[(size_t)i * CC + c];
        acc += sc * g_sm[(size_t)i * CC + t];
    }
    atomicAdd(&g_G[c * CC + t], acc);
}
__global__ void k_gramsq() {
    __shared__ float sh[256];
    int t = threadIdx.x;
    float acc = 0.f;
    for (int i = t; i < CC * CC; i += 256) { float g = g_G[i]; acc += g * g; }
    float s = blockReduceSum(acc, sh);
    if (t == 0) g_acc[3] = s;
}
__global__ void k_finalize(float* __restrict__ out_loss) {
    float n2 = g_acc[0] - 2.f * g_acc[1] + g_acc[3];
    float link = sqrtf(fmaxf(n2, 0.f)) / ((float)TWO_N * (float)TWO_N);
    out_loss[0] = link + g_acc[2] / (float)TWO_N;
}

// ----------------------------- MHA2 -----------------------------
__global__ void k_transpose128(const float* __restrict__ wi) {  // g_wt[k,n] = wi[n,k]
    int idx = blockIdx.x * 256 + threadIdx.x;
    if (idx >= DIM * DIM) return;
    int n = idx >> 7, k = idx & 127;
    g_wt[(size_t)k * DIM + n] = wi[(size_t)n * DIM + k];
}
__global__ void k_kvproj(const float* __restrict__ wi, const float* __restrict__ bi) {
    int c = blockIdx.x;       // pooled row
    int which = blockIdx.y;   // 0=K, 1=V
    int t = threadIdx.x;      // 128
    __shared__ float prow[DIM];
    prow[t] = g_pooled[(size_t)c * DIM + t];
    __syncthreads();
    const float4* row4 = reinterpret_cast<const float4*>(wi + (size_t)(DIM + which * DIM + t) * DIM);
    float acc = bi[DIM + which * DIM + t];
    #pragma unroll
    for (int k = 0; k < 32; k++) {
        float4 r = row4[k];
        acc += r.x * prow[4 * k] + r.y * prow[4 * k + 1]
             + r.z * prow[4 * k + 2] + r.w * prow[4 * k + 3];
    }
    (which ? g_vp2 : g_kp2)[(size_t)c * DIM + t] = acc;
}

#define K_LD 129
// K staged in smem; V read from L1/L2; warp-per-head softmax.
__global__ void k_mha2(const float* __restrict__ wo, const float* __restrict__ bo,
                       float* __restrict__ out_skill) {
    extern __shared__ float kp_s[];     // [CC][K_LD]
    __shared__ float qrow[DIM];
    __shared__ float lg[HH][CC];
    __shared__ float o_s[DIM];
    int t = threadIdx.x;  // 128
    int w = t >> 5, lane = t & 31;
    for (int i = t; i < CC * DIM; i += 128) {
        int j = i >> 7, d = i & 127;
        kp_s[j * K_LD + d] = g_kp2[i];
    }
    __syncthreads();
    int n0 = blockIdx.x * 16;
    for (int q = 0; q < 16; q++) {
        int n = n0 + q;
        qrow[t] = g_qp2[(size_t)n * DIM + t];
        __syncthreads();
        for (int pos = t; pos < HH * CC; pos += 128) {
            int h = pos / CC, j = pos % CC;
            float acc = 0.f;
            #pragma unroll 8
            for (int d = 0; d < HD; d++)
                acc += qrow[h * HD + d] * kp_s[j * K_LD + h * HD + d];
            lg[h][j] = acc * INV_SQRT_HD;
        }
        __syncthreads();
        {   // warp w handles head w softmax over CC
            float mx = -1e30f;
            for (int j = lane; j < CC; j += 32) mx = fmaxf(mx, lg[w][j]);
            #pragma unroll
            for (int o = 16; o > 0; o >>= 1) mx = fmaxf(mx, __shfl_xor_sync(0xffffffff, mx, o));
            float sm = 0.f;
            for (int j = lane; j < CC; j += 32) { float e = expf(lg[w][j] - mx); lg[w][j] = e; sm += e; }
            #pragma unroll
            for (int o = 16; o > 0; o >>= 1) sm += __shfl_xor_sync(0xffffffff, sm, o);
            float inv = 1.f / sm;
            for (int j = lane; j < CC; j += 32) lg[w][j] *= inv;
        }
        __syncthreads();
        {   // ctx: o_s[t] = sum_j p[h(t)][j] * V[j][t]
            float acc = 0.f;
            for (int j = 0; j < CC; j++) acc += lg[w][j] * g_vp2[(size_t)j * DIM + t];
            o_s[t] = acc;
        }
        __syncthreads();
        {   // out proj (float4) + residuals
            const float4* row4 = reinterpret_cast<const float4*>(wo + (size_t)t * DIM);
            float acc = bo[t];
            #pragma unroll
            for (int k = 0; k < 32; k++) {
                float4 r = row4[k];
                acc += r.x * o_s[4 * k] + r.y * o_s[4 * k + 1]
                     + r.z * o_s[4 * k + 2] + r.w * o_s[4 * k + 3];
            }
            out_skill[(size_t)n * DIM + t] = 2.f * g_emb[(size_t)n * DIM + t] + acc;
        }
        __syncthreads();
    }
}

// ----------------------------- host launch -----------------------------
extern "C" void kernel_launch(void* const* d_in, const int* in_sizes, int n_in,
                              void* d_out, int out_size) {
    const float* demand = (const float*)d_in[0];
    const float* supply = (const float*)d_in[1];
    const float* skill  = (const float*)d_in[2];
    const int*   eidx   = (const int*)d_in[3];
    const float* eattr  = (const float*)d_in[4];
    const float* w_fuse = (const float*)d_in[5];
    const float* b_fuse = (const float*)d_in[6];
    const float* m1wi   = (const float*)d_in[7];
    const float* m1bi   = (const float*)d_in[8];
    const float* m1wo   = (const float*)d_in[9];
    const float* m1bo   = (const float*)d_in[10];
    const float* m2wi   = (const float*)d_in[11];
    const float* m2bi   = (const float*)d_in[12];
    const float* m2wo   = (const float*)d_in[13];
    const float* m2bo   = (const float*)d_in[14];
    const float* sender = (const float*)d_in[15];
    const float* recv   = (const float*)d_in[16];
    const float* W0     = (const float*)d_in[17];
    const float* b0     = (const float*)d_in[18];
    const float* W1     = (const float*)d_in[19];
    const float* b1     = (const float*)d_in[20];
    const float* Wp     = (const float*)d_in[21];
    const float* bp     = (const float*)d_in[22];
    float* out = (float*)d_out;
    const int* src = eidx;
    const int* dst = eidx + EE;

    cudaFuncSetAttribute(k_mha2, cudaFuncAttributeMaxDynamicSharedMemorySize,
                         CC * K_LD * (int)sizeof(float) + 1024);

    float *p_cat2, *p_fused, *p_xw, *p_tmpA, *p_tmpB, *p_emb, *p_sm, *p_wt, *p_qp2;
    float *p_qv, *p_qp1, *p_U, *p_c, *p_wqt, *p_Mk, *p_Zcat, *p_zb, *p_seq_att;
    cudaGetSymbolAddress((void**)&p_cat2, g_cat2);
    cudaGetSymbolAddress((void**)&p_fused, g_fused);
    cudaGetSymbolAddress((void**)&p_xw, g_xw);
    cudaGetSymbolAddress((void**)&p_tmpA, g_tmpA);
    cudaGetSymbolAddress((void**)&p_tmpB, g_tmpB);
    cudaGetSymbolAddress((void**)&p_emb, g_emb);
    cudaGetSymbolAddress((void**)&p_sm, g_sm);
    cudaGetSymbolAddress((void**)&p_wt, g_wt);
    cudaGetSymbolAddress((void**)&p_qp2, g_qp2);
    cudaGetSymbolAddress((void**)&p_qv, g_qv);
    cudaGetSymbolAddress((void**)&p_qp1, g_qp1);
    cudaGetSymbolAddress((void**)&p_U, g_U);
    cudaGetSymbolAddress((void**)&p_c, g_c);
    cudaGetSymbolAddress((void**)&p_wqt, g_wqt);
    cudaGetSymbolAddress((void**)&p_Mk, g_Mk);
    cudaGetSymbolAddress((void**)&p_Zcat, g_Zcat);
    cudaGetSymbolAddress((void**)&p_zb, g_zb);
    cudaGetSymbolAddress((void**)&p_seq_att, g_seq_att);

    k_init<<<64, 256>>>(sender, recv);
    k_seqsum<<<dim3(2, 24), 128>>>(demand, supply);
    k_seqsum2<<<2, 128>>>();

    // MHA1 as GEMM chain
    k_wqt<<<64, 256>>>(m1wi);
    k_mk<<<256, 256>>>(m1wi);
    k_zcat<<<512, 128>>>(m1wi, m1wo);
    k_zb<<<1, 128>>>(m1wo, m1bo, m1bi);
    k_qv<<<TWO_N * DIM / 256, 256>>>(skill);
    k_sgemm<<<dim3(1, TWO_N / 64), 256>>>(p_qv, p_wqt, m1bi, p_qp1, TWO_N, DIM, DIM, DIM);
    k_sgemm<<<dim3(4, TWO_N / 64), 256>>>(p_qp1, p_Mk, nullptr, p_U, TWO_N, 4 * DIM, DIM, 4 * DIM);
    k_attn1<<<TWO_N, 128>>>(demand, supply, m1bi);
    k_sgemm<<<dim3(1, TWO_N / 64), 256>>>(p_c, p_Zcat, p_zb, p_seq_att, TWO_N, DIM, 4 * DIM, DIM);

    k_cat2<<<TWO_N, 128>>>(skill, out + OUT_CAT);
    k_sgemm<<<dim3(1, TWO_N / 64), 256>>>(p_cat2, w_fuse, b_fuse, p_fused, TWO_N, DIM, 2 * DIM, DIM);
    k_tanhprep<<<TWO_N * DIM / 256, 256>>>(sender, recv);
    k_scores<<<1184, 256>>>();
    k_predg<<<TWO_N, 256>>>(out + OUT_PRED);
    k_dinv<<<24, 256>>>();

    // dense GCN (2 layers)
    for (int l = 0; l < 2; l++) {
        const float* srcbuf = (l == 0) ? p_fused : p_tmpA;
        k_sgemm<<<dim3(1, TWO_N / 64), 256>>>(srcbuf, W0 + (size_t)l * DIM * DIM, nullptr, p_xw,
                                              TWO_N, DIM, DIM, DIM);
        k_scale_rows<<<TWO_N * DIM / 256, 256>>>();
        k_dense_agg<<<TWO_N / 32, 256>>>();
        k_dense_combine<<<TWO_N * DIM / 256, 256>>>(srcbuf, p_tmpA, b0, l);
    }

    // sparse GCN: CSR build once, then 2 gather layers
    k_degsp<<<EE / 256, 256>>>(dst, eattr);
    k_dinvsp<<<24, 256>>>();
    k_count<<<EE / 256, 256>>>(dst);
    k_scan<<<1, 1024>>>();
    k_fillcsr<<<EE / 256, 256>>>(src, dst, eattr);
    for (int l = 0; l < 2; l++) {
        const float* srcbuf = (l == 0) ? p_fused : p_tmpB;
        k_sgemm<<<dim3(1, TWO_N / 64), 256>>>(srcbuf, W1 + (size_t)l * DIM * DIM, nullptr, p_xw,
                                              TWO_N, DIM, DIM, DIM);
        k_spgather<<<TWO_N, 128>>>(srcbuf, p_tmpB, b1, l);
    }

    k_addemb<<<TWO_N * DIM / 256, 256>>>();

    // diff-pool
    k_sgemm<<<dim3(1, TWO_N / 64), 256>>>(p_emb, Wp, bp, p_sm, TWO_N, CC, DIM, CC);
    k_softmax_s<<<TWO_N, 128>>>();
    k_pooled<<<dim3(25, 8), 128>>>();
    k_scatterA<<<EE / 256, 256>>>(src, dst, eattr);
    k_cross<<<EE / 8, 256>>>(src, dst, eattr);
    k_normA<<<EE / 256, 256>>>(src, dst);
    k_gram<<<dim3(CC, 8), 128>>>();
    k_gramsq<<<1, 256>>>();
    k_finalize<<<1, 1>>>(out + OUT_LOSS);

    // MHA2
    k_transpose128<<<DIM * DIM / 256, 256>>>(m2wi);
    k_sgemm<<<dim3(1, TWO_N / 64), 256>>>(p_emb, p_wt, m2bi, p_qp2, TWO_N, DIM, DIM, DIM);
    k_kvproj<<<dim3(CC, 2), 128>>>(m2wi, m2bi);
    k_mha2<<<TWO_N / 16, 128, CC * K_LD * sizeof(float) + 1024>>>(m2wo, m2bo, out + OUT_SKILL);
}